// round 7
// baseline (speedup 1.0000x reference)
#include <cuda_runtime.h>
#include <math.h>

#define BB 4
#define NN 2048
#define HH 4
#define DD 128
#define QB 64    // queries per CTA in tensor attention
#define PCK 40   // packed-row stride (words)

// swizzled word-offset within a packed tile row (uint2 granularity kept even)
#define SL(row, w) ((unsigned)(row) * PCK + (((unsigned)(w)) ^ (2u * ((unsigned)(row) & 7u))))

// ---- device scratch ----
__device__ float g_h[(size_t)BB * HH * NN * DD];     // [b,h,n,o]
__device__ float g_ht[(size_t)BB * HH * DD * NN];    // [b,h,o,n]
__device__ float g_att[(size_t)BB * HH * NN * DD];   // alpha @ h  [b,h,n,o]
__device__ float g_es[BB * HH * NN];
__device__ float g_es2[BB * HH * NN];
__device__ float g_ed[BB * HH * NN];
__device__ float g_ed2[BB * HH * NN];
__device__ unsigned g_wpt[DD][512];                  // out_proj_w, packed tf32 [col][k]

// ---- packed fp32x2 helpers ----
#define FMA2(d, a, b, c) \
    asm("fma.rn.f32x2 %0, %1, %2, %3;" : "=l"(d) : "l"(a), "l"(b), "l"(c))
#define PACK2(d, x) \
    asm("mov.b64 %0, {%1, %1};" : "=l"(d) : "r"(__float_as_uint(x)))
__device__ __forceinline__ float lo2(unsigned long long v) {
    return __uint_as_float((unsigned)(v & 0xffffffffull));
}
__device__ __forceinline__ float hi2(unsigned long long v) {
    return __uint_as_float((unsigned)(v >> 32));
}

__device__ __forceinline__ unsigned f2tf32(float x) {
    unsigned r;
    asm("cvt.rna.tf32.f32 %0, %1;" : "=r"(r) : "f"(x));
    return r;
}
__device__ __forceinline__ int pslot8(int j) {  // (m, m+4) adjacent within 8-group
    return ((j & 3) << 1) + (j >> 2);
}

__device__ __forceinline__ void mma_tf32(float* c, unsigned a0, unsigned a1,
                                         unsigned a2, unsigned a3,
                                         unsigned b0, unsigned b1) {
    asm volatile(
        "mma.sync.aligned.m16n8k8.row.col.f32.tf32.tf32.f32 "
        "{%0,%1,%2,%3}, {%4,%5,%6,%7}, {%8,%9}, {%0,%1,%2,%3};"
        : "+f"(c[0]), "+f"(c[1]), "+f"(c[2]), "+f"(c[3])
        : "r"(a0), "r"(a1), "r"(a2), "r"(a3), "r"(b0), "r"(b1));
}

// ============================================================
// Kernel 0: pack out_proj_w -> tf32, [col][k] with 8-group pslot
// ============================================================
__global__ void k_prepw(const float* __restrict__ Wp) {
    int idx = blockIdx.x * 256 + threadIdx.x;  // 65536 total
    int k = idx >> 7, col = idx & 127;
    g_wpt[col][(k & ~7) + pslot8(k & 7)] = f2tf32(Wp[k * DD + col]);
}

// ============================================================
// Kernel 1: h = x @ W per head; writes g_h and transposed g_ht
// ============================================================
__global__ void k_project(const float* __restrict__ x, const float* __restrict__ W) {
    __shared__ __align__(16) float xs_t[DD][20];
    __shared__ float ht_s[DD][17];
    int b = blockIdx.y, n0 = blockIdx.x * 16, tid = threadIdx.x;
#pragma unroll
    for (int i = 0; i < 8; i++) {
        int j = tid + i * 256;
        int r = j >> 7, k = j & 127;
        xs_t[k][r] = x[((size_t)b * NN + n0 + r) * DD + k];
    }
    __syncthreads();
    int col = tid & 127, rs = tid >> 7;
    for (int h = 0; h < HH; h++) {
        const float* Wh = W + h * DD * DD + col;
        unsigned long long acc[4] = {0ull, 0ull, 0ull, 0ull};
#pragma unroll 8
        for (int k = 0; k < DD; k++) {
            unsigned long long wp;
            PACK2(wp, Wh[k * DD]);
            ulonglong2 x01 = *(const ulonglong2*)&xs_t[k][rs * 8];
            ulonglong2 x23 = *(const ulonglong2*)&xs_t[k][rs * 8 + 4];
            FMA2(acc[0], wp, x01.x, acc[0]);
            FMA2(acc[1], wp, x01.y, acc[1]);
            FMA2(acc[2], wp, x23.x, acc[2]);
            FMA2(acc[3], wp, x23.y, acc[3]);
        }
        size_t base = ((size_t)(b * HH + h) * NN + n0 + rs * 8) * DD + col;
#pragma unroll
        for (int p = 0; p < 4; p++) {
            float vlo = lo2(acc[p]), vhi = hi2(acc[p]);
            g_h[base + (size_t)(2 * p) * DD] = vlo;
            g_h[base + (size_t)(2 * p + 1) * DD] = vhi;
            ht_s[col][rs * 8 + 2 * p] = vlo;
            ht_s[col][rs * 8 + 2 * p + 1] = vhi;
        }
        __syncthreads();
        {
            int o = tid >> 1, j0 = (tid & 1) * 8;
            float* dst = g_ht + ((size_t)(b * HH + h) * DD + o) * NN + n0 + j0;
#pragma unroll
            for (int j = 0; j < 8; j++) dst[j] = ht_s[o][j0 + j];
        }
        __syncthreads();
    }
}

// ============================================================
// Kernel 2: scores -> 4 exps per (b,h,n)
// ============================================================
__global__ void k_scores(const float* __restrict__ a) {
    int warp = (blockIdx.x * blockDim.x + threadIdx.x) >> 5;
    int lane = threadIdx.x & 31;
    int hidx = (warp / NN) % HH;
    float4 hv = ((const float4*)(g_h + (size_t)warp * DD))[lane];
    float4 av = ((const float4*)(a + hidx * 2 * DD))[lane];
    float4 bv = ((const float4*)(a + hidx * 2 * DD + DD))[lane];
    float s = hv.x * av.x + hv.y * av.y + hv.z * av.z + hv.w * av.w;
    float d = hv.x * bv.x + hv.y * bv.y + hv.z * bv.z + hv.w * bv.w;
#pragma unroll
    for (int off = 16; off; off >>= 1) {
        s += __shfl_down_sync(0xffffffffu, s, off);
        d += __shfl_down_sync(0xffffffffu, d, off);
    }
    if (!lane) {
        g_es[warp] = expf(s);
        g_es2[warp] = expf(0.2f * s);
        g_ed[warp] = expf(d);
        g_ed2[warp] = expf(0.2f * d);
    }
}

// ============================================================
// Kernel 3: warp-MMA (tf32) attention. CTA = (b,h) x 64 queries.
// w tile staged in w_pack (computed once by alpha producer);
// all packed-tile smem accesses conflict-free (stride 40 + XOR).
// Warp tile: 32q x 32o (B fragments reused 2x).
// ============================================================
__global__ void __launch_bounds__(256, 3)
k_attn_mma(const int* __restrict__ adj, float* __restrict__ alpha, int write_alpha) {
    __shared__ float ed_s[NN], ed2_s[NN];                   // 16 KB
    __shared__ unsigned adjb[QB][66];                       // 16.9 KB
    __shared__ __align__(16) unsigned h_pack[DD * PCK];     // 20 KB
    __shared__ __align__(16) unsigned w_pack[QB * PCK];     // 10 KB
    __shared__ float esr[QB], es2r[QB], izr[QB];

    int b = blockIdx.z, hh = blockIdx.y, q0 = blockIdx.x * QB;
    int bh = b * HH + hh;
    int tid = threadIdx.x, wid = tid >> 5, lane = tid & 31;

    const float* edp = g_ed + bh * NN;
    const float* ed2p = g_ed2 + bh * NN;
    for (int m = tid; m < NN; m += 256) {
        ed_s[m] = edp[m];
        ed2_s[m] = ed2p[m];
    }
    if (tid < QB) {
        int idx = bh * NN + q0 + tid;
        esr[tid] = g_es[idx];
        es2r[tid] = g_es2[idx];
    }
    __syncthreads();

    // ---- pack adjacency rows into bitmasks ----
    {
        int r = tid >> 2, seg = tid & 3;
        const int4* arow =
            (const int4*)(adj + ((size_t)(b * NN + q0 + r)) * NN) + seg * 128;
#pragma unroll 4
        for (int w16 = 0; w16 < 16; w16++) {
            unsigned word = 0;
#pragma unroll
            for (int u = 0; u < 8; u++) {
                int4 v = arow[w16 * 8 + u];
                word |= (v.x != 0 ? 1u : 0u) << (u * 4);
                word |= (v.y != 0 ? 1u : 0u) << (u * 4 + 1);
                word |= (v.z != 0 ? 1u : 0u) << (u * 4 + 2);
                word |= (v.w != 0 ? 1u : 0u) << (u * 4 + 3);
            }
            adjb[r][seg * 16 + w16] = word;
        }
    }
    __syncthreads();

    // ---- Z per row from bits ----
#pragma unroll
    for (int rr = 0; rr < 8; rr++) {
        int r = wid * 8 + rr;
        float es = esr[r], es2 = es2r[r];
        float z = 0.f;
        for (int j = 0; j < NN / 32; j++) {
            unsigned w = adjb[r][j];
            if ((w >> lane) & 1u) {
                int m = j * 32 + lane;
                z += fmaxf(es * ed_s[m], es2 * ed2_s[m]);
            }
        }
#pragma unroll
        for (int off = 16; off; off >>= 1) z += __shfl_down_sync(0xffffffffu, z, off);
        if (!lane) izr[r] = z;
    }
    __syncthreads();
    if (tid < QB) izr[tid] = 1.0f / izr[tid];
    __syncthreads();

    // ---- main loop ----
    float acc[2][4][4];
#pragma unroll
    for (int i = 0; i < 2; i++)
#pragma unroll
        for (int j = 0; j < 4; j++)
#pragma unroll
            for (int k = 0; k < 4; k++) acc[i][j][k] = 0.f;

    // h staging mapping: thread owns row o, 16-m half
    int o = tid >> 1, half = tid & 1;
    const float4* hp4 =
        (const float4*)(g_ht + ((size_t)bh * DD + o) * NN) + half * 4;

    // alpha/w producer mapping: 8 m per thread, one q row
    int q = tid >> 2, grp = tid & 3, mh = grp * 8;
    float* alrow = alpha + ((size_t)bh * NN + q0 + q) * NN;
    float p1 = esr[q] * izr[q], p2 = es2r[q] * izr[q];

    // warp tile: 32q x 32o
    int wq0 = (wid >> 2) * 32, oh = (wid & 3) * 32;
    int frow = lane >> 2, tig = lane & 3, fcol = tig * 2;

    for (int c = 0; c < NN / 32; c++) {
        // ---- producers: compute w (8 values) + prefetch h (16 floats) ----
        float4 e0 = *(const float4*)&ed_s[c * 32 + mh];
        float4 e1 = *(const float4*)&ed_s[c * 32 + mh + 4];
        float4 f0 = *(const float4*)&ed2_s[c * 32 + mh];
        float4 f1 = *(const float4*)&ed2_s[c * 32 + mh + 4];
        unsigned pb = adjb[q][c] >> mh;
        float wv[8];
        wv[0] = (pb & 1u) ? fmaxf(p1 * e0.x, p2 * f0.x) : 0.f;
        wv[1] = (pb & 2u) ? fmaxf(p1 * e0.y, p2 * f0.y) : 0.f;
        wv[2] = (pb & 4u) ? fmaxf(p1 * e0.z, p2 * f0.z) : 0.f;
        wv[3] = (pb & 8u) ? fmaxf(p1 * e0.w, p2 * f0.w) : 0.f;
        wv[4] = (pb & 16u) ? fmaxf(p1 * e1.x, p2 * f1.x) : 0.f;
        wv[5] = (pb & 32u) ? fmaxf(p1 * e1.y, p2 * f1.y) : 0.f;
        wv[6] = (pb & 64u) ? fmaxf(p1 * e1.z, p2 * f1.z) : 0.f;
        wv[7] = (pb & 128u) ? fmaxf(p1 * e1.w, p2 * f1.w) : 0.f;
        if (write_alpha) {
            *(float4*)(alrow + c * 32 + mh) = make_float4(wv[0], wv[1], wv[2], wv[3]);
            *(float4*)(alrow + c * 32 + mh + 4) = make_float4(wv[4], wv[5], wv[6], wv[7]);
        }

        float hvf[16];
#pragma unroll
        for (int i = 0; i < 4; i++) {
            float4 v = hp4[c * 8 + i];
            hvf[i * 4] = v.x; hvf[i * 4 + 1] = v.y;
            hvf[i * 4 + 2] = v.z; hvf[i * 4 + 3] = v.w;
        }

        __syncthreads();  // previous chunk's MMA reads done

        // ---- stage tiles (all conflict-free) ----
#pragma unroll
        for (int g = 0; g < 2; g++) {
            int ks = half * 2 + g;
#pragma unroll
            for (int t = 0; t < 4; t++) {
                uint2 val;
                val.x = f2tf32(hvf[g * 8 + t]);
                val.y = f2tf32(hvf[g * 8 + t + 4]);
                *(uint2*)&h_pack[SL(o, ks * 8 + t * 2)] = val;
            }
        }
#pragma unroll
        for (int j = 0; j < 4; j++) {
            uint2 val;
            val.x = f2tf32(wv[j]);
            val.y = f2tf32(wv[j + 4]);
            *(uint2*)&w_pack[SL(q, grp * 8 + j * 2)] = val;
        }
        __syncthreads();

        // ---- MMA: 32q x 32o x 32m per warp ----
#pragma unroll
        for (int ks = 0; ks < 4; ks++) {
            int wcol = ks * 8 + fcol;
            uint2 aA0 = *(const uint2*)&w_pack[SL(wq0 + frow, wcol)];
            uint2 aA1 = *(const uint2*)&w_pack[SL(wq0 + 8 + frow, wcol)];
            uint2 aB0 = *(const uint2*)&w_pack[SL(wq0 + 16 + frow, wcol)];
            uint2 aB1 = *(const uint2*)&w_pack[SL(wq0 + 24 + frow, wcol)];
#pragma unroll
            for (int nt = 0; nt < 4; nt++) {
                uint2 bb = *(const uint2*)&h_pack[SL(oh + nt * 8 + frow, wcol)];
                mma_tf32(acc[0][nt], aA0.x, aA1.x, aA0.y, aA1.y, bb.x, bb.y);
                mma_tf32(acc[1][nt], aB0.x, aB1.x, aB0.y, aB1.y, bb.x, bb.y);
            }
        }
    }

    // epilogue
#pragma unroll
    for (int qb = 0; qb < 2; qb++)
#pragma unroll
        for (int nt = 0; nt < 4; nt++) {
            int qq = q0 + wq0 + qb * 16 + frow;
            int oo = oh + nt * 8 + fcol;
            float* p0 = g_att + ((size_t)bh * NN + qq) * DD + oo;
            *(float2*)p0 = make_float2(acc[qb][nt][0], acc[qb][nt][1]);
            *(float2*)(p0 + (size_t)8 * DD) = make_float2(acc[qb][nt][2], acc[qb][nt][3]);
        }
}

// ============================================================
// Kernel 4: out = concat(g_att) @ Wp + bias, tf32 warp-MMA
// ============================================================
__global__ void __launch_bounds__(256, 2)
k_outproj_mma(const float* __restrict__ bias, float* __restrict__ out) {
    __shared__ __align__(16) unsigned a_pack[QB][PCK];   // 10 KB
    __shared__ __align__(16) unsigned b_pack[DD][PCK];   // 20 KB
    __shared__ float bias_s[DD];

    int tid = threadIdx.x, wid = tid >> 5, lane = tid & 31;
    int row0 = blockIdx.x * QB;
    if (tid < DD) bias_s[tid] = bias[tid];

    float acc[8][4];
#pragma unroll
    for (int i = 0; i < 8; i++)
#pragma unroll
        for (int j = 0; j < 4; j++) acc[i][j] = 0.f;

    int wq0 = (wid >> 1) * 16, oh = (wid & 1) * 64;
    int frow = lane >> 2, fcol = (lane & 3) * 2;
    int sr = tid >> 2, sg = tid & 3;

    for (int c = 0; c < 16; c++) {
        int head = c >> 2, o0 = (c & 3) * 32;
        int grow = row0 + sr;
        int bb_ = grow >> 11, nn_ = grow & 2047;
        const float4* ap =
            (const float4*)(g_att + ((size_t)(bb_ * HH + head) * NN + nn_) * DD + o0 + sg * 8);
        float4 v0 = ap[0], v1 = ap[1];
        uint4 wv[4];
#pragma unroll
        for (int i = 0; i < 4; i++) {
            int j = tid + i * 256;
            int col = j >> 3, f4 = j & 7;
            wv[i] = *(const uint4*)&g_wpt[col][c * 32 + f4 * 4];
        }

        __syncthreads();

        float av[8] = {v0.x, v0.y, v0.z, v0.w, v1.x, v1.y, v1.z, v1.w};
#pragma unroll
        for (int j = 0; j < 8; j++) a_pack[sr][sg * 8 + pslot8(j)] = f2tf32(av[j]);
#pragma unroll
        for (int i = 0; i < 4; i++) {
            int j = tid + i * 256;
            int col = j >> 3, f4 = j & 7;
            *(uint4*)&b_pack[col][f4 * 4] = wv[i];
        }
        __syncthreads();

#pragma unroll
        for (int ks = 0; ks < 4; ks++) {
            uint2 aLo = *(const uint2*)&a_pack[wq0 + frow][ks * 8 + fcol];
            uint2 aHi = *(const uint2*)&a_pack[wq0 + 8 + frow][ks * 8 + fcol];
#pragma unroll
            for (int nt = 0; nt < 8; nt++) {
                uint2 bb = *(const uint2*)&b_pack[oh + nt * 8 + frow][ks * 8 + fcol];
                mma_tf32(acc[nt], aLo.x, aHi.x, aLo.y, aHi.y, bb.x, bb.y);
            }
        }
    }

#pragma unroll
    for (int nt = 0; nt < 8; nt++) {
        int rr = row0 + wq0 + frow;
        int oo = oh + nt * 8 + fcol;
        float b0 = bias_s[oo], b1 = bias_s[oo + 1];
        float* p0 = out + (size_t)rr * DD + oo;
        *(float2*)p0 = make_float2(acc[nt][0] + b0, acc[nt][1] + b1);
        *(float2*)(p0 + (size_t)8 * DD) = make_float2(acc[nt][2] + b0, acc[nt][3] + b1);
    }
}

// ============================================================
extern "C" void kernel_launch(void* const* d_in, const int* in_sizes, int n_in,
                              void* d_out, int out_size) {
    const float* x    = (const float*)d_in[0];
    const int*   adj  = (const int*)d_in[1];
    const float* W    = (const float*)d_in[2];
    const float* a    = (const float*)d_in[3];
    const float* Wp   = (const float*)d_in[4];
    const float* bias = (const float*)d_in[5];

    const size_t OUT_E = (size_t)BB * NN * DD;
    const size_t AL_E  = (size_t)BB * HH * NN * NN;

    float* outp = nullptr;
    float* alphap = nullptr;
    int write_alpha = 0, write_out = 0;

    if ((size_t)out_size >= OUT_E + AL_E) {
        outp = (float*)d_out;
        alphap = (float*)d_out + OUT_E;
        write_alpha = 1;
        write_out = 1;
    } else if ((size_t)out_size >= AL_E) {
        alphap = (float*)d_out;
        write_alpha = 1;
    } else {
        outp = (float*)d_out;
        write_out = 1;
    }
    if (!alphap) alphap = g_att;  // dummy, never stored to when !write_alpha

    k_project<<<dim3(NN / 16, BB), 256>>>(x, W);
    k_scores<<<(BB * HH * NN * 32) / 256, 256>>>(a);
    if (write_out) k_prepw<<<256, 256>>>(Wp);
    k_attn_mma<<<dim3(NN / QB, HH, BB), 256>>>(adj, alphap, write_alpha);
    if (write_out)
        k_outproj_mma<<<(BB * NN) / QB, 256>>>(bias, outp);
}

// round 9
// speedup vs baseline: 1.2319x; 1.2319x over previous
#include <cuda_runtime.h>
#include <math.h>

#define BB 4
#define NN 2048
#define HH 4
#define DD 128
#define QB 64    // queries per CTA in tensor attention
#define PCK 40   // packed-row stride (words)
#define AJW 68   // adjb row stride (words, 16B-aligned)

// swizzled word-offset within a packed tile row (uint2 granularity kept even)
#define SL(row, w) ((unsigned)(row) * PCK + (((unsigned)(w)) ^ (2u * ((unsigned)(row) & 7u))))

// ---- device scratch ----
__device__ float g_h[(size_t)BB * HH * NN * DD];          // [b,h,n,o]
__device__ __align__(16) unsigned g_htp[(size_t)BB * HH * 64 * DD * 32]; // tf32 tiles
__device__ float g_att[(size_t)BB * HH * NN * DD];        // alpha @ h  [b,h,n,o]
__device__ float g_es[BB * HH * NN];
__device__ float g_es2[BB * HH * NN];
__device__ float g_ed[BB * HH * NN];
__device__ float g_ed2[BB * HH * NN];
__device__ unsigned g_wpt[DD][512];                       // out_proj_w tf32 [col][k]
__device__ __align__(16) unsigned g_adjb[(size_t)BB * NN * 64]; // adjacency bitmask

// ---- packed fp32x2 helpers ----
#define FMA2(d, a, b, c) \
    asm("fma.rn.f32x2 %0, %1, %2, %3;" : "=l"(d) : "l"(a), "l"(b), "l"(c))
#define PACK2(d, x) \
    asm("mov.b64 %0, {%1, %1};" : "=l"(d) : "r"(__float_as_uint(x)))
__device__ __forceinline__ float lo2(unsigned long long v) {
    return __uint_as_float((unsigned)(v & 0xffffffffull));
}
__device__ __forceinline__ float hi2(unsigned long long v) {
    return __uint_as_float((unsigned)(v >> 32));
}

__device__ __forceinline__ unsigned f2tf32(float x) {
    unsigned r;
    asm("cvt.rna.tf32.f32 %0, %1;" : "=r"(r) : "f"(x));
    return r;
}
__device__ __forceinline__ int pslot8(int j) {  // (m, m+4) adjacent within 8-group
    return ((j & 3) << 1) + (j >> 2);
}

__device__ __forceinline__ void mma_tf32(float* c, unsigned a0, unsigned a1,
                                         unsigned a2, unsigned a3,
                                         unsigned b0, unsigned b1) {
    asm volatile(
        "mma.sync.aligned.m16n8k8.row.col.f32.tf32.tf32.f32 "
        "{%0,%1,%2,%3}, {%4,%5,%6,%7}, {%8,%9}, {%0,%1,%2,%3};"
        : "+f"(c[0]), "+f"(c[1]), "+f"(c[2]), "+f"(c[3])
        : "r"(a0), "r"(a1), "r"(a2), "r"(a3), "r"(b0), "r"(b1));
}

// ============================================================
// Kernel -1: pack adjacency -> bitmask. warp per row.
// ============================================================
__global__ void k_packadj(const int* __restrict__ adj) {
    int wid = threadIdx.x >> 5, lane = threadIdx.x & 31;
    size_t row = (size_t)blockIdx.x * 8 + wid;
    const int4* arow = (const int4*)(adj + row * NN);
    unsigned* dst = g_adjb + row * 64;
#pragma unroll 4
    for (int it = 0; it < 16; it++) {
        int4 v = arow[it * 32 + lane];
        unsigned nib = (v.x != 0 ? 1u : 0u) | (v.y != 0 ? 2u : 0u) |
                       (v.z != 0 ? 4u : 0u) | (v.w != 0 ? 8u : 0u);
        unsigned nv = nib << (4 * (lane & 7));
        nv |= __shfl_xor_sync(0xffffffffu, nv, 1);
        nv |= __shfl_xor_sync(0xffffffffu, nv, 2);
        nv |= __shfl_xor_sync(0xffffffffu, nv, 4);
        if ((lane & 7) == 0) dst[it * 4 + (lane >> 3)] = nv;
    }
}

// ============================================================
// Kernel 0: pack out_proj_w -> tf32, [col][k] with 8-group pslot
// ============================================================
__global__ void k_prepw(const float* __restrict__ Wp) {
    int idx = blockIdx.x * 256 + threadIdx.x;
    int k = idx >> 7, col = idx & 127;
    g_wpt[col][(k & ~7) + pslot8(k & 7)] = f2tf32(Wp[k * DD + col]);
}

// ============================================================
// Kernel 1: h = x @ W per head; writes g_h and tf32 tiles g_htp
// ============================================================
__global__ void k_project(const float* __restrict__ x, const float* __restrict__ W) {
    __shared__ __align__(16) float xs_t[DD][20];
    __shared__ float ht_s[DD][17];
    int b = blockIdx.y, n0 = blockIdx.x * 16, tid = threadIdx.x;
#pragma unroll
    for (int i = 0; i < 8; i++) {
        int j = tid + i * 256;
        int r = j >> 7, k = j & 127;
        xs_t[k][r] = x[((size_t)b * NN + n0 + r) * DD + k];
    }
    __syncthreads();
    int col = tid & 127, rs = tid >> 7;
    for (int h = 0; h < HH; h++) {
        const float* Wh = W + h * DD * DD + col;
        unsigned long long acc[4] = {0ull, 0ull, 0ull, 0ull};
#pragma unroll 8
        for (int k = 0; k < DD; k++) {
            unsigned long long wp;
            PACK2(wp, Wh[k * DD]);
            ulonglong2 x01 = *(const ulonglong2*)&xs_t[k][rs * 8];
            ulonglong2 x23 = *(const ulonglong2*)&xs_t[k][rs * 8 + 4];
            FMA2(acc[0], wp, x01.x, acc[0]);
            FMA2(acc[1], wp, x01.y, acc[1]);
            FMA2(acc[2], wp, x23.x, acc[2]);
            FMA2(acc[3], wp, x23.y, acc[3]);
        }
        size_t base = ((size_t)(b * HH + h) * NN + n0 + rs * 8) * DD + col;
#pragma unroll
        for (int p = 0; p < 4; p++) {
            float vlo = lo2(acc[p]), vhi = hi2(acc[p]);
            g_h[base + (size_t)(2 * p) * DD] = vlo;
            g_h[base + (size_t)(2 * p + 1) * DD] = vhi;
            ht_s[col][rs * 8 + 2 * p] = vlo;
            ht_s[col][rs * 8 + 2 * p + 1] = vhi;
        }
        __syncthreads();
        // write tf32 tile words: chunk = n0>>5, m_local = (n0&31)+j0+j
        {
            int o = tid >> 1, j0 = (tid & 1) * 8;
            int chunk = n0 >> 5;
            int mbase = (n0 & 31) + j0;       // 8-aligned
            int ks = mbase >> 3;
            unsigned* dst =
                g_htp + (((size_t)(b * HH + h) * 64 + chunk) * DD + o) * 32 + ks * 8;
#pragma unroll
            for (int j = 0; j < 8; j++)
                dst[2 * (j & 3) + (j >> 2)] = f2tf32(ht_s[o][j0 + j]);
        }
        __syncthreads();
    }
}

// ============================================================
// Kernel 2: scores -> 4 exps per (b,h,n)
// ============================================================
__global__ void k_scores(const float* __restrict__ a) {
    int warp = (blockIdx.x * blockDim.x + threadIdx.x) >> 5;
    int lane = threadIdx.x & 31;
    int hidx = (warp / NN) % HH;
    float4 hv = ((const float4*)(g_h + (size_t)warp * DD))[lane];
    float4 av = ((const float4*)(a + hidx * 2 * DD))[lane];
    float4 bv = ((const float4*)(a + hidx * 2 * DD + DD))[lane];
    float s = hv.x * av.x + hv.y * av.y + hv.z * av.z + hv.w * av.w;
    float d = hv.x * bv.x + hv.y * bv.y + hv.z * bv.z + hv.w * bv.w;
#pragma unroll
    for (int off = 16; off; off >>= 1) {
        s += __shfl_down_sync(0xffffffffu, s, off);
        d += __shfl_down_sync(0xffffffffu, d, off);
    }
    if (!lane) {
        g_es[warp] = expf(s);
        g_es2[warp] = expf(0.2f * s);
        g_ed[warp] = expf(d);
        g_ed2[warp] = expf(0.2f * d);
    }
}

// ============================================================
// Kernel 3: warp-MMA (tf32) attention, double-buffered pipeline.
// CTA = (b,h) x 64 queries. Warp tile: 32q x 32o.
// ============================================================
__global__ void __launch_bounds__(256, 2)
k_attn_mma(float* __restrict__ alpha, int write_alpha) {
    __shared__ __align__(16) float ed_s[NN], ed2_s[NN];      // 16 KB
    __shared__ __align__(16) unsigned adjb[QB][AJW];         // 17.4 KB
    __shared__ __align__(16) unsigned h_pack[2][DD * PCK];   // 40 KB
    __shared__ __align__(16) unsigned w_pack[2][QB * PCK];   // 20 KB
    __shared__ float esr[QB], es2r[QB], izr[QB];

    int b = blockIdx.z, hh = blockIdx.y, q0 = blockIdx.x * QB;
    int bh = b * HH + hh;
    int tid = threadIdx.x, wid = tid >> 5, lane = tid & 31;

    const float* edp = g_ed + bh * NN;
    const float* ed2p = g_ed2 + bh * NN;
    for (int m = tid; m < NN; m += 256) {
        ed_s[m] = edp[m];
        ed2_s[m] = ed2p[m];
    }
    if (tid < QB) {
        int idx = bh * NN + q0 + tid;
        esr[tid] = g_es[idx];
        es2r[tid] = g_es2[idx];
    }
    // load adjacency bitmasks: row r = tid>>2, 16 words each
    {
        int r = tid >> 2, j0 = (tid & 3) * 16;
        const uint4* src =
            (const uint4*)(g_adjb + ((size_t)(b * NN + q0 + r)) * 64 + j0);
#pragma unroll
        for (int u = 0; u < 4; u++) *(uint4*)&adjb[r][j0 + u * 4] = src[u];
    }
    __syncthreads();

    // ---- Z per row from bits ----
#pragma unroll
    for (int rr = 0; rr < 8; rr++) {
        int r = wid * 8 + rr;
        float es = esr[r], es2 = es2r[r];
        float z = 0.f;
        for (int j = 0; j < NN / 32; j++) {
            unsigned w = adjb[r][j];
            if ((w >> lane) & 1u) {
                int m = j * 32 + lane;
                z += fmaxf(es * ed_s[m], es2 * ed2_s[m]);
            }
        }
#pragma unroll
        for (int off = 16; off; off >>= 1) z += __shfl_down_sync(0xffffffffu, z, off);
        if (!lane) izr[r] = z;
    }
    __syncthreads();
    if (tid < QB) izr[tid] = 1.0f / izr[tid];
    __syncthreads();

    // ---- pipelined main loop ----
    float acc[2][4][4];
#pragma unroll
    for (int i = 0; i < 2; i++)
#pragma unroll
        for (int j = 0; j < 4; j++)
#pragma unroll
            for (int k = 0; k < 4; k++) acc[i][j][k] = 0.f;

    // h staging mapping: thread owns row o, 16-word half
    int o = tid >> 1, half = tid & 1;
    const uint4* hsrc =
        (const uint4*)(g_htp + ((size_t)bh * 64 * DD + o) * 32) + half * 4;

    // w producer mapping: 8 m per thread, one q row
    int q = tid >> 2, grp = tid & 3, mh = grp * 8;
    float* alrow = alpha + ((size_t)bh * NN + q0 + q) * NN;
    float p1 = esr[q] * izr[q], p2 = es2r[q] * izr[q];

    // warp tile: 32q x 32o
    int wq0 = (wid >> 2) * 32, oh = (wid & 3) * 32;
    int frow = lane >> 2, fcol = (lane & 3) * 2;

    uint4 hreg[4];
    float wv[8];

    // prologue: chunk 0 into regs
    {
#pragma unroll
        for (int u = 0; u < 4; u++) hreg[u] = hsrc[u];
        float4 e0 = *(const float4*)&ed_s[mh];
        float4 e1 = *(const float4*)&ed_s[mh + 4];
        float4 f0 = *(const float4*)&ed2_s[mh];
        float4 f1 = *(const float4*)&ed2_s[mh + 4];
        unsigned pb = adjb[q][0] >> mh;
        wv[0] = (pb & 1u) ? fmaxf(p1 * e0.x, p2 * f0.x) : 0.f;
        wv[1] = (pb & 2u) ? fmaxf(p1 * e0.y, p2 * f0.y) : 0.f;
        wv[2] = (pb & 4u) ? fmaxf(p1 * e0.z, p2 * f0.z) : 0.f;
        wv[3] = (pb & 8u) ? fmaxf(p1 * e0.w, p2 * f0.w) : 0.f;
        wv[4] = (pb & 16u) ? fmaxf(p1 * e1.x, p2 * f1.x) : 0.f;
        wv[5] = (pb & 32u) ? fmaxf(p1 * e1.y, p2 * f1.y) : 0.f;
        wv[6] = (pb & 64u) ? fmaxf(p1 * e1.z, p2 * f1.z) : 0.f;
        wv[7] = (pb & 128u) ? fmaxf(p1 * e1.w, p2 * f1.w) : 0.f;
        if (write_alpha) {
            *(float4*)(alrow + mh) = make_float4(wv[0], wv[1], wv[2], wv[3]);
            *(float4*)(alrow + mh + 4) = make_float4(wv[4], wv[5], wv[6], wv[7]);
        }
    }

    for (int c = 0; c < NN / 32; c++) {
        int buf = c & 1;
        __syncthreads();  // A: MMA(c-1) finished; buf free

        // stage chunk c from regs (no conversions for h)
        {
            const uint2* hr2 = (const uint2*)hreg;
#pragma unroll
            for (int g = 0; g < 2; g++) {
                int ks = half * 2 + g;
#pragma unroll
                for (int t = 0; t < 4; t++)
                    *(uint2*)&h_pack[buf][SL(o, ks * 8 + 2 * t)] = hr2[g * 4 + t];
            }
#pragma unroll
            for (int j = 0; j < 4; j++) {
                uint2 val;
                val.x = f2tf32(wv[j]);
                val.y = f2tf32(wv[j + 4]);
                *(uint2*)&w_pack[buf][SL(q, grp * 8 + 2 * j)] = val;
            }
        }

        // prefetch chunk c+1 into regs + alpha write
        if (c < NN / 32 - 1) {
            int cn = c + 1;
#pragma unroll
            for (int u = 0; u < 4; u++) hreg[u] = hsrc[(size_t)cn * DD * 8 + u];
            float4 e0 = *(const float4*)&ed_s[cn * 32 + mh];
            float4 e1 = *(const float4*)&ed_s[cn * 32 + mh + 4];
            float4 f0 = *(const float4*)&ed2_s[cn * 32 + mh];
            float4 f1 = *(const float4*)&ed2_s[cn * 32 + mh + 4];
            unsigned pb = adjb[q][cn] >> mh;
            wv[0] = (pb & 1u) ? fmaxf(p1 * e0.x, p2 * f0.x) : 0.f;
            wv[1] = (pb & 2u) ? fmaxf(p1 * e0.y, p2 * f0.y) : 0.f;
            wv[2] = (pb & 4u) ? fmaxf(p1 * e0.z, p2 * f0.z) : 0.f;
            wv[3] = (pb & 8u) ? fmaxf(p1 * e0.w, p2 * f0.w) : 0.f;
            wv[4] = (pb & 16u) ? fmaxf(p1 * e1.x, p2 * f1.x) : 0.f;
            wv[5] = (pb & 32u) ? fmaxf(p1 * e1.y, p2 * f1.y) : 0.f;
            wv[6] = (pb & 64u) ? fmaxf(p1 * e1.z, p2 * f1.z) : 0.f;
            wv[7] = (pb & 128u) ? fmaxf(p1 * e1.w, p2 * f1.w) : 0.f;
            if (write_alpha) {
                *(float4*)(alrow + cn * 32 + mh) =
                    make_float4(wv[0], wv[1], wv[2], wv[3]);
                *(float4*)(alrow + cn * 32 + mh + 4) =
                    make_float4(wv[4], wv[5], wv[6], wv[7]);
            }
        }

        __syncthreads();  // B: chunk c staged

        // MMA: 32q x 32o x 32m per warp
#pragma unroll
        for (int ks = 0; ks < 4; ks++) {
            int wcol = ks * 8 + fcol;
            uint2 aA0 = *(const uint2*)&w_pack[buf][SL(wq0 + frow, wcol)];
            uint2 aA1 = *(const uint2*)&w_pack[buf][SL(wq0 + 8 + frow, wcol)];
            uint2 aB0 = *(const uint2*)&w_pack[buf][SL(wq0 + 16 + frow, wcol)];
            uint2 aB1 = *(const uint2*)&w_pack[buf][SL(wq0 + 24 + frow, wcol)];
#pragma unroll
            for (int nt = 0; nt < 4; nt++) {
                uint2 bb = *(const uint2*)&h_pack[buf][SL(oh + nt * 8 + frow, wcol)];
                mma_tf32(acc[0][nt], aA0.x, aA1.x, aA0.y, aA1.y, bb.x, bb.y);
                mma_tf32(acc[1][nt], aB0.x, aB1.x, aB0.y, aB1.y, bb.x, bb.y);
            }
        }
    }

    // epilogue
#pragma unroll
    for (int qb = 0; qb < 2; qb++)
#pragma unroll
        for (int nt = 0; nt < 4; nt++) {
            int qq = q0 + wq0 + qb * 16 + frow;
            int oo = oh + nt * 8 + fcol;
            float* p0 = g_att + ((size_t)bh * NN + qq) * DD + oo;
            *(float2*)p0 = make_float2(acc[qb][nt][0], acc[qb][nt][1]);
            *(float2*)(p0 + (size_t)8 * DD) = make_float2(acc[qb][nt][2], acc[qb][nt][3]);
        }
}

// ============================================================
// Kernel 4: out = concat(g_att) @ Wp + bias, tf32 warp-MMA
// ============================================================
__global__ void __launch_bounds__(256, 2)
k_outproj_mma(const float* __restrict__ bias, float* __restrict__ out) {
    __shared__ __align__(16) unsigned a_pack[QB][PCK];
    __shared__ __align__(16) unsigned b_pack[DD][PCK];
    __shared__ float bias_s[DD];

    int tid = threadIdx.x, wid = tid >> 5, lane = tid & 31;
    int row0 = blockIdx.x * QB;
    if (tid < DD) bias_s[tid] = bias[tid];

    float acc[8][4];
#pragma unroll
    for (int i = 0; i < 8; i++)
#pragma unroll
        for (int j = 0; j < 4; j++) acc[i][j] = 0.f;

    int wq0 = (wid >> 1) * 16, oh = (wid & 1) * 64;
    int frow = lane >> 2, fcol = (lane & 3) * 2;
    int sr = tid >> 2, sg = tid & 3;

    for (int c = 0; c < 16; c++) {
        int head = c >> 2, o0 = (c & 3) * 32;
        int grow = row0 + sr;
        int bb_ = grow >> 11, nn_ = grow & 2047;
        const float4* ap =
            (const float4*)(g_att + ((size_t)(bb_ * HH + head) * NN + nn_) * DD + o0 + sg * 8);
        float4 v0 = ap[0], v1 = ap[1];
        uint4 wv[4];
#pragma unroll
        for (int i = 0; i < 4; i++) {
            int j = tid + i * 256;
            int col = j >> 3, f4 = j & 7;
            wv[i] = *(const uint4*)&g_wpt[col][c * 32 + f4 * 4];
        }

        __syncthreads();

        float av[8] = {v0.x, v0.y, v0.z, v0.w, v1.x, v1.y, v1.z, v1.w};
#pragma unroll
        for (int j = 0; j < 8; j++) a_pack[sr][sg * 8 + pslot8(j)] = f2tf32(av[j]);
#pragma unroll
        for (int i = 0; i < 4; i++) {
            int j = tid + i * 256;
            int col = j >> 3, f4 = j & 7;
            *(uint4*)&b_pack[col][f4 * 4] = wv[i];
        }
        __syncthreads();

#pragma unroll
        for (int ks = 0; ks < 4; ks++) {
            uint2 aLo = *(const uint2*)&a_pack[wq0 + frow][ks * 8 + fcol];
            uint2 aHi = *(const uint2*)&a_pack[wq0 + 8 + frow][ks * 8 + fcol];
#pragma unroll
            for (int nt = 0; nt < 8; nt++) {
                uint2 bb = *(const uint2*)&b_pack[oh + nt * 8 + frow][ks * 8 + fcol];
                mma_tf32(acc[nt], aLo.x, aHi.x, aLo.y, aHi.y, bb.x, bb.y);
            }
        }
    }

#pragma unroll
    for (int nt = 0; nt < 8; nt++) {
        int rr = row0 + wq0 + frow;
        int oo = oh + nt * 8 + fcol;
        float b0 = bias_s[oo], b1 = bias_s[oo + 1];
        float* p0 = out + (size_t)rr * DD + oo;
        *(float2*)p0 = make_float2(acc[nt][0] + b0, acc[nt][1] + b1);
        *(float2*)(p0 + (size_t)8 * DD) = make_float2(acc[nt][2] + b0, acc[nt][3] + b1);
    }
}

// ============================================================
extern "C" void kernel_launch(void* const* d_in, const int* in_sizes, int n_in,
                              void* d_out, int out_size) {
    const float* x    = (const float*)d_in[0];
    const int*   adj  = (const int*)d_in[1];
    const float* W    = (const float*)d_in[2];
    const float* a    = (const float*)d_in[3];
    const float* Wp   = (const float*)d_in[4];
    const float* bias = (const float*)d_in[5];

    const size_t OUT_E = (size_t)BB * NN * DD;
    const size_t AL_E  = (size_t)BB * HH * NN * NN;

    float* outp = nullptr;
    float* alphap = nullptr;
    int write_alpha = 0, write_out = 0;

    if ((size_t)out_size >= OUT_E + AL_E) {
        outp = (float*)d_out;
        alphap = (float*)d_out + OUT_E;
        write_alpha = 1;
        write_out = 1;
    } else if ((size_t)out_size >= AL_E) {
        alphap = (float*)d_out;
        write_alpha = 1;
    } else {
        outp = (float*)d_out;
        write_out = 1;
    }
    if (!alphap) alphap = g_att;  // dummy, never stored to when !write_alpha

    k_packadj<<<(BB * NN) / 8, 256>>>(adj);
    k_project<<<dim3(NN / 16, BB), 256>>>(x, W);
    k_scores<<<(BB * HH * NN * 32) / 256, 256>>>(a);
    if (write_out) k_prepw<<<256, 256>>>(Wp);
    k_attn_mma<<<dim3(NN / QB, HH, BB), 256>>>(alphap, write_alpha);
    if (write_out)
        k_outproj_mma<<<(BB * NN) / QB, 256>>>(bias, outp);
}

// round 10
// speedup vs baseline: 1.6824x; 1.3657x over previous
#include <cuda_runtime.h>
#include <math.h>

#define BB 4
#define NN 2048
#define HH 4
#define DD 128
#define QB 64    // queries per CTA in tensor attention
#define PCK 40   // packed-row stride (words) — outproj kernel
#define PCKH 24  // fp16 packed-row stride (words) — attn kernel
#define AJW 68   // adjb row stride (words, 16B-aligned)

// ---- device scratch ----
__device__ float g_h[(size_t)BB * HH * NN * DD];          // [b,h,n,o]
__device__ __align__(16) unsigned g_htp[(size_t)BB * HH * 64 * DD * 16]; // fp16 tiles
__device__ float g_att[(size_t)BB * HH * NN * DD];        // alpha @ h  [b,h,n,o]
__device__ float g_es[BB * HH * NN];
__device__ float g_es2[BB * HH * NN];
__device__ float g_ed[BB * HH * NN];
__device__ float g_ed2[BB * HH * NN];
__device__ unsigned g_wpt[DD][512];                       // out_proj_w tf32 [col][k]
__device__ __align__(16) unsigned g_adjb[(size_t)BB * NN * 64]; // adjacency bitmask

// ---- packed fp32x2 helpers ----
#define FMA2(d, a, b, c) \
    asm("fma.rn.f32x2 %0, %1, %2, %3;" : "=l"(d) : "l"(a), "l"(b), "l"(c))
#define PACK2(d, x) \
    asm("mov.b64 %0, {%1, %1};" : "=l"(d) : "r"(__float_as_uint(x)))
__device__ __forceinline__ float lo2(unsigned long long v) {
    return __uint_as_float((unsigned)(v & 0xffffffffull));
}
__device__ __forceinline__ float hi2(unsigned long long v) {
    return __uint_as_float((unsigned)(v >> 32));
}

__device__ __forceinline__ unsigned f2tf32(float x) {
    unsigned r;
    asm("cvt.rna.tf32.f32 %0, %1;" : "=r"(r) : "f"(x));
    return r;
}
__device__ __forceinline__ unsigned f2h2(float lo, float hi) {
    unsigned r;
    asm("cvt.rn.f16x2.f32 %0, %1, %2;" : "=r"(r) : "f"(hi), "f"(lo));
    return r;
}
__device__ __forceinline__ int pslot8(int j) {  // (m, m+4) adjacent within 8-group
    return ((j & 3) << 1) + (j >> 2);
}

__device__ __forceinline__ void mma_tf32(float* c, unsigned a0, unsigned a1,
                                         unsigned a2, unsigned a3,
                                         unsigned b0, unsigned b1) {
    asm volatile(
        "mma.sync.aligned.m16n8k8.row.col.f32.tf32.tf32.f32 "
        "{%0,%1,%2,%3}, {%4,%5,%6,%7}, {%8,%9}, {%0,%1,%2,%3};"
        : "+f"(c[0]), "+f"(c[1]), "+f"(c[2]), "+f"(c[3])
        : "r"(a0), "r"(a1), "r"(a2), "r"(a3), "r"(b0), "r"(b1));
}
__device__ __forceinline__ void mma_f16(float* c, unsigned a0, unsigned a1,
                                        unsigned a2, unsigned a3,
                                        unsigned b0, unsigned b1) {
    asm volatile(
        "mma.sync.aligned.m16n8k16.row.col.f32.f16.f16.f32 "
        "{%0,%1,%2,%3}, {%4,%5,%6,%7}, {%8,%9}, {%0,%1,%2,%3};"
        : "+f"(c[0]), "+f"(c[1]), "+f"(c[2]), "+f"(c[3])
        : "r"(a0), "r"(a1), "r"(a2), "r"(a3), "r"(b0), "r"(b1));
}

// ============================================================
// Kernel -1: pack adjacency -> bitmask. warp per row.
// ============================================================
__global__ void k_packadj(const int* __restrict__ adj) {
    int wid = threadIdx.x >> 5, lane = threadIdx.x & 31;
    size_t row = (size_t)blockIdx.x * 8 + wid;
    const int4* arow = (const int4*)(adj + row * NN);
    unsigned* dst = g_adjb + row * 64;
#pragma unroll 4
    for (int it = 0; it < 16; it++) {
        int4 v = arow[it * 32 + lane];
        unsigned nib = (v.x != 0 ? 1u : 0u) | (v.y != 0 ? 2u : 0u) |
                       (v.z != 0 ? 4u : 0u) | (v.w != 0 ? 8u : 0u);
        unsigned nv = nib << (4 * (lane & 7));
        nv |= __shfl_xor_sync(0xffffffffu, nv, 1);
        nv |= __shfl_xor_sync(0xffffffffu, nv, 2);
        nv |= __shfl_xor_sync(0xffffffffu, nv, 4);
        if ((lane & 7) == 0) dst[it * 4 + (lane >> 3)] = nv;
    }
}

// ============================================================
// Kernel 0: pack out_proj_w -> tf32, [col][k] with 8-group pslot
// ============================================================
__global__ void k_prepw(const float* __restrict__ Wp) {
    int idx = blockIdx.x * 256 + threadIdx.x;
    int k = idx >> 7, col = idx & 127;
    g_wpt[col][(k & ~7) + pslot8(k & 7)] = f2tf32(Wp[k * DD + col]);
}

// ============================================================
// Kernel 1: h = x @ W per head; writes g_h and fp16 tiles g_htp
// ============================================================
__global__ void k_project(const float* __restrict__ x, const float* __restrict__ W) {
    __shared__ __align__(16) float xs_t[DD][20];
    __shared__ float ht_s[DD][17];
    int b = blockIdx.y, n0 = blockIdx.x * 16, tid = threadIdx.x;
#pragma unroll
    for (int i = 0; i < 8; i++) {
        int j = tid + i * 256;
        int r = j >> 7, k = j & 127;
        xs_t[k][r] = x[((size_t)b * NN + n0 + r) * DD + k];
    }
    __syncthreads();
    int col = tid & 127, rs = tid >> 7;
    for (int h = 0; h < HH; h++) {
        const float* Wh = W + h * DD * DD + col;
        unsigned long long acc[4] = {0ull, 0ull, 0ull, 0ull};
#pragma unroll 8
        for (int k = 0; k < DD; k++) {
            unsigned long long wp;
            PACK2(wp, Wh[k * DD]);
            ulonglong2 x01 = *(const ulonglong2*)&xs_t[k][rs * 8];
            ulonglong2 x23 = *(const ulonglong2*)&xs_t[k][rs * 8 + 4];
            FMA2(acc[0], wp, x01.x, acc[0]);
            FMA2(acc[1], wp, x01.y, acc[1]);
            FMA2(acc[2], wp, x23.x, acc[2]);
            FMA2(acc[3], wp, x23.y, acc[3]);
        }
        size_t base = ((size_t)(b * HH + h) * NN + n0 + rs * 8) * DD + col;
#pragma unroll
        for (int p = 0; p < 4; p++) {
            float vlo = lo2(acc[p]), vhi = hi2(acc[p]);
            g_h[base + (size_t)(2 * p) * DD] = vlo;
            g_h[base + (size_t)(2 * p + 1) * DD] = vhi;
            ht_s[col][rs * 8 + 2 * p] = vlo;
            ht_s[col][rs * 8 + 2 * p + 1] = vhi;
        }
        __syncthreads();
        // write fp16 tile words (pair-packed, pslot order within 8-word groups)
        {
            int o = tid >> 1, j0 = (tid & 1) * 8;
            int chunk = n0 >> 5;
            int mbase = (n0 & 31) + j0;   // 8-aligned
            int w0 = mbase >> 1;          // word base (4-aligned)
            unsigned* dst =
                g_htp + (((size_t)(b * HH + h) * 64 + chunk) * DD + o) * 16;
#pragma unroll
            for (int t = 0; t < 4; t++) {
                int w = w0 + t;
                int slot = (w >> 3) * 8 + 2 * (w & 3) + ((w & 7) >> 2);
                dst[slot] = f2h2(ht_s[o][j0 + 2 * t], ht_s[o][j0 + 2 * t + 1]);
            }
        }
        __syncthreads();
    }
}

// ============================================================
// Kernel 2: scores -> 4 exps per (b,h,n)
// ============================================================
__global__ void k_scores(const float* __restrict__ a) {
    int warp = (blockIdx.x * blockDim.x + threadIdx.x) >> 5;
    int lane = threadIdx.x & 31;
    int hidx = (warp / NN) % HH;
    float4 hv = ((const float4*)(g_h + (size_t)warp * DD))[lane];
    float4 av = ((const float4*)(a + hidx * 2 * DD))[lane];
    float4 bv = ((const float4*)(a + hidx * 2 * DD + DD))[lane];
    float s = hv.x * av.x + hv.y * av.y + hv.z * av.z + hv.w * av.w;
    float d = hv.x * bv.x + hv.y * bv.y + hv.z * bv.z + hv.w * bv.w;
#pragma unroll
    for (int off = 16; off; off >>= 1) {
        s += __shfl_down_sync(0xffffffffu, s, off);
        d += __shfl_down_sync(0xffffffffu, d, off);
    }
    if (!lane) {
        g_es[warp] = expf(s);
        g_es2[warp] = expf(0.2f * s);
        g_ed[warp] = expf(d);
        g_ed2[warp] = expf(0.2f * d);
    }
}

// ============================================================
// Kernel 3: fp16 warp-MMA attention, double-buffered, 1 barrier
// per chunk. CTA = (b,h) x 64 queries. Warp tile: 32q x 32o.
// ============================================================
__global__ void __launch_bounds__(256, 3)
k_attn_mma(float* __restrict__ alpha, int write_alpha) {
    __shared__ __align__(16) float ed_s[NN], ed2_s[NN];        // 16 KB
    __shared__ __align__(16) unsigned adjb[QB][AJW];           // 17.4 KB
    __shared__ __align__(16) unsigned h_pack[2][DD * PCKH];    // 24.6 KB
    __shared__ __align__(16) unsigned w_pack[2][QB * PCKH];    // 12.3 KB
    __shared__ float esr[QB], es2r[QB], izr[QB];

    int b = blockIdx.z, hh = blockIdx.y, q0 = blockIdx.x * QB;
    int bh = b * HH + hh;
    int tid = threadIdx.x, wid = tid >> 5, lane = tid & 31;

    const float* edp = g_ed + bh * NN;
    const float* ed2p = g_ed2 + bh * NN;
    for (int m = tid; m < NN; m += 256) {
        ed_s[m] = edp[m];
        ed2_s[m] = ed2p[m];
    }
    if (tid < QB) {
        int idx = bh * NN + q0 + tid;
        esr[tid] = g_es[idx];
        es2r[tid] = g_es2[idx];
    }
    {
        int r = tid >> 2, j0 = (tid & 3) * 16;
        const uint4* src =
            (const uint4*)(g_adjb + ((size_t)(b * NN + q0 + r)) * 64 + j0);
#pragma unroll
        for (int u = 0; u < 4; u++) *(uint4*)&adjb[r][j0 + u * 4] = src[u];
    }
    __syncthreads();

    // ---- Z per row from bits ----
#pragma unroll
    for (int rr = 0; rr < 8; rr++) {
        int r = wid * 8 + rr;
        float es = esr[r], es2 = es2r[r];
        float z = 0.f;
        for (int j = 0; j < NN / 32; j++) {
            unsigned w = adjb[r][j];
            if ((w >> lane) & 1u) {
                int m = j * 32 + lane;
                z += fmaxf(es * ed_s[m], es2 * ed2_s[m]);
            }
        }
#pragma unroll
        for (int off = 16; off; off >>= 1) z += __shfl_down_sync(0xffffffffu, z, off);
        if (!lane) izr[r] = z;
    }
    __syncthreads();
    if (tid < QB) izr[tid] = 1.0f / izr[tid];
    __syncthreads();

    // ---- pipelined main loop ----
    float acc[2][4][4];
#pragma unroll
    for (int i = 0; i < 2; i++)
#pragma unroll
        for (int j = 0; j < 4; j++)
#pragma unroll
            for (int k = 0; k < 4; k++) acc[i][j][k] = 0.f;

    // h staging: thread owns row o, interleaved half (slots 4h..4h+3, 8+4h..)
    int o = tid >> 1, half = tid & 1;
    const uint4* hsrc = (const uint4*)(g_htp + ((size_t)bh * 64 * DD + o) * 16);

    // w producer: thread q = tid>>2, g = tid&3; m = {2g,2g+1}+{0,8,16,24}
    int q = tid >> 2, g = tid & 3;
    float* alrow = alpha + ((size_t)bh * NN + q0 + q) * NN;
    float p1 = esr[q] * izr[q], p2 = es2r[q] * izr[q];

    // warp tile: 32q x 32o
    int wq0 = (wid >> 2) * 32, oh = (wid & 3) * 32;
    int frow = lane >> 2, tig = lane & 3, fcol = tig * 2;

    uint4 hreg[2];
    float wv[8];

#define PRODUCE_W(cc)                                                          \
    do {                                                                       \
        int i0 = (cc) * 32 + 2 * g;                                            \
        float2 ea = *(const float2*)&ed_s[i0];                                 \
        float2 eb = *(const float2*)&ed_s[i0 + 8];                             \
        float2 ec = *(const float2*)&ed_s[i0 + 16];                            \
        float2 ed = *(const float2*)&ed_s[i0 + 24];                            \
        float2 fa = *(const float2*)&ed2_s[i0];                                \
        float2 fb = *(const float2*)&ed2_s[i0 + 8];                            \
        float2 fc = *(const float2*)&ed2_s[i0 + 16];                           \
        float2 fd = *(const float2*)&ed2_s[i0 + 24];                           \
        unsigned pb = adjb[q][cc] >> (2 * g);                                  \
        wv[0] = (pb & 0x1u) ? fmaxf(p1 * ea.x, p2 * fa.x) : 0.f;               \
        wv[1] = (pb & 0x2u) ? fmaxf(p1 * ea.y, p2 * fa.y) : 0.f;               \
        wv[2] = (pb & 0x100u) ? fmaxf(p1 * eb.x, p2 * fb.x) : 0.f;             \
        wv[3] = (pb & 0x200u) ? fmaxf(p1 * eb.y, p2 * fb.y) : 0.f;             \
        wv[4] = (pb & 0x10000u) ? fmaxf(p1 * ec.x, p2 * fc.x) : 0.f;           \
        wv[5] = (pb & 0x20000u) ? fmaxf(p1 * ec.y, p2 * fc.y) : 0.f;           \
        wv[6] = (pb & 0x1000000u) ? fmaxf(p1 * ed.x, p2 * fd.x) : 0.f;         \
        wv[7] = (pb & 0x2000000u) ? fmaxf(p1 * ed.y, p2 * fd.y) : 0.f;         \
        if (write_alpha) {                                                     \
            float* ar = alrow + (cc) * 32 + 2 * g;                             \
            *(float2*)ar = make_float2(wv[0], wv[1]);                          \
            *(float2*)(ar + 8) = make_float2(wv[2], wv[3]);                    \
            *(float2*)(ar + 16) = make_float2(wv[4], wv[5]);                   \
            *(float2*)(ar + 24) = make_float2(wv[6], wv[7]);                   \
        }                                                                      \
    } while (0)

    // prologue: chunk 0
    hreg[0] = hsrc[half];
    hreg[1] = hsrc[2 + half];
    PRODUCE_W(0);

    for (int c = 0; c < NN / 32; c++) {
        int buf = c & 1;
        // stage chunk c (safe: MMA(c-2) done via barrier of iter c-1;
        // MMA(c-1) uses the other buffer)
        *(uint4*)&h_pack[buf][o * PCKH + 4 * half] = hreg[0];
        *(uint4*)&h_pack[buf][o * PCKH + 8 + 4 * half] = hreg[1];
        {
            uint2 v0, v1;
            v0.x = f2h2(wv[0], wv[1]);
            v0.y = f2h2(wv[2], wv[3]);
            v1.x = f2h2(wv[4], wv[5]);
            v1.y = f2h2(wv[6], wv[7]);
            *(uint2*)&w_pack[buf][q * PCKH + 2 * g] = v0;
            *(uint2*)&w_pack[buf][q * PCKH + 8 + 2 * g] = v1;
        }

        // prefetch chunk c+1
        if (c < NN / 32 - 1) {
            int cn = c + 1;
            hreg[0] = hsrc[(size_t)cn * DD * 4 + half];
            hreg[1] = hsrc[(size_t)cn * DD * 4 + 2 + half];
            PRODUCE_W(cn);
        }

        __syncthreads();  // chunk c staged (and MMA(c-1) complete)

        // MMA: 32q x 32o x 32m per warp (fp16, k16)
#pragma unroll
        for (int ks = 0; ks < 2; ks++) {
            int wcol = ks * 8 + 2 * tig;
            uint2 aA0 = *(const uint2*)&w_pack[buf][(wq0 + frow) * PCKH + wcol];
            uint2 aA1 = *(const uint2*)&w_pack[buf][(wq0 + 8 + frow) * PCKH + wcol];
            uint2 aB0 = *(const uint2*)&w_pack[buf][(wq0 + 16 + frow) * PCKH + wcol];
            uint2 aB1 = *(const uint2*)&w_pack[buf][(wq0 + 24 + frow) * PCKH + wcol];
#pragma unroll
            for (int nt = 0; nt < 4; nt++) {
                uint2 bb =
                    *(const uint2*)&h_pack[buf][(oh + nt * 8 + frow) * PCKH + wcol];
                mma_f16(acc[0][nt], aA0.x, aA1.x, aA0.y, aA1.y, bb.x, bb.y);
                mma_f16(acc[1][nt], aB0.x, aB1.x, aB0.y, aB1.y, bb.x, bb.y);
            }
        }
    }
#undef PRODUCE_W

    // epilogue
#pragma unroll
    for (int qb = 0; qb < 2; qb++)
#pragma unroll
        for (int nt = 0; nt < 4; nt++) {
            int qq = q0 + wq0 + qb * 16 + frow;
            int oo = oh + nt * 8 + fcol;
            float* p0 = g_att + ((size_t)bh * NN + qq) * DD + oo;
            *(float2*)p0 = make_float2(acc[qb][nt][0], acc[qb][nt][1]);
            *(float2*)(p0 + (size_t)8 * DD) = make_float2(acc[qb][nt][2], acc[qb][nt][3]);
        }
}

// ============================================================
// Kernel 4: out = concat(g_att) @ Wp + bias, tf32 warp-MMA
// ============================================================
__global__ void __launch_bounds__(256, 2)
k_outproj_mma(const float* __restrict__ bias, float* __restrict__ out) {
    __shared__ __align__(16) unsigned a_pack[QB][PCK];
    __shared__ __align__(16) unsigned b_pack[DD][PCK];
    __shared__ float bias_s[DD];

    int tid = threadIdx.x, wid = tid >> 5, lane = tid & 31;
    int row0 = blockIdx.x * QB;
    if (tid < DD) bias_s[tid] = bias[tid];

    float acc[8][4];
#pragma unroll
    for (int i = 0; i < 8; i++)
#pragma unroll
        for (int j = 0; j < 4; j++) acc[i][j] = 0.f;

    int wq0 = (wid >> 1) * 16, oh = (wid & 1) * 64;
    int frow = lane >> 2, fcol = (lane & 3) * 2;
    int sr = tid >> 2, sg = tid & 3;

    for (int c = 0; c < 16; c++) {
        int head = c >> 2, o0 = (c & 3) * 32;
        int grow = row0 + sr;
        int bb_ = grow >> 11, nn_ = grow & 2047;
        const float4* ap =
            (const float4*)(g_att + ((size_t)(bb_ * HH + head) * NN + nn_) * DD + o0 + sg * 8);
        float4 v0 = ap[0], v1 = ap[1];
        uint4 wv[4];
#pragma unroll
        for (int i = 0; i < 4; i++) {
            int j = tid + i * 256;
            int col = j >> 3, f4 = j & 7;
            wv[i] = *(const uint4*)&g_wpt[col][c * 32 + f4 * 4];
        }

        __syncthreads();

        float av[8] = {v0.x, v0.y, v0.z, v0.w, v1.x, v1.y, v1.z, v1.w};
#pragma unroll
        for (int j = 0; j < 8; j++) a_pack[sr][sg * 8 + pslot8(j)] = f2tf32(av[j]);
#pragma unroll
        for (int i = 0; i < 4; i++) {
            int j = tid + i * 256;
            int col = j >> 3, f4 = j & 7;
            *(uint4*)&b_pack[col][f4 * 4] = wv[i];
        }
        __syncthreads();

#pragma unroll
        for (int ks = 0; ks < 4; ks++) {
            uint2 aLo = *(const uint2*)&a_pack[wq0 + frow][ks * 8 + fcol];
            uint2 aHi = *(const uint2*)&a_pack[wq0 + 8 + frow][ks * 8 + fcol];
#pragma unroll
            for (int nt = 0; nt < 8; nt++) {
                uint2 bb = *(const uint2*)&b_pack[oh + nt * 8 + frow][ks * 8 + fcol];
                mma_tf32(acc[nt], aLo.x, aHi.x, aLo.y, aHi.y, bb.x, bb.y);
            }
        }
    }

#pragma unroll
    for (int nt = 0; nt < 8; nt++) {
        int rr = row0 + wq0 + frow;
        int oo = oh + nt * 8 + fcol;
        float b0 = bias_s[oo], b1 = bias_s[oo + 1];
        float* p0 = out + (size_t)rr * DD + oo;
        *(float2*)p0 = make_float2(acc[nt][0] + b0, acc[nt][1] + b1);
        *(float2*)(p0 + (size_t)8 * DD) = make_float2(acc[nt][2] + b0, acc[nt][3] + b1);
    }
}

// ============================================================
extern "C" void kernel_launch(void* const* d_in, const int* in_sizes, int n_in,
                              void* d_out, int out_size) {
    const float* x    = (const float*)d_in[0];
    const int*   adj  = (const int*)d_in[1];
    const float* W    = (const float*)d_in[2];
    const float* a    = (const float*)d_in[3];
    const float* Wp   = (const float*)d_in[4];
    const float* bias = (const float*)d_in[5];

    const size_t OUT_E = (size_t)BB * NN * DD;
    const size_t AL_E  = (size_t)BB * HH * NN * NN;

    float* outp = nullptr;
    float* alphap = nullptr;
    int write_alpha = 0, write_out = 0;

    if ((size_t)out_size >= OUT_E + AL_E) {
        outp = (float*)d_out;
        alphap = (float*)d_out + OUT_E;
        write_alpha = 1;
        write_out = 1;
    } else if ((size_t)out_size >= AL_E) {
        alphap = (float*)d_out;
        write_alpha = 1;
    } else {
        outp = (float*)d_out;
        write_out = 1;
    }
    if (!alphap) alphap = g_att;  // dummy, never stored to when !write_alpha

    k_packadj<<<(BB * NN) / 8, 256>>>(adj);
    k_project<<<dim3(NN / 16, BB), 256>>>(x, W);
    k_scores<<<(BB * HH * NN * 32) / 256, 256>>>(a);
    if (write_out) k_prepw<<<256, 256>>>(Wp);
    k_attn_mma<<<dim3(NN / QB, HH, BB), 256>>>(alphap, write_alpha);
    if (write_out)
        k_outproj_mma<<<(BB * NN) / QB, 256>>>(bias, outp);
}

// round 11
// speedup vs baseline: 1.7284x; 1.0273x over previous
#include <cuda_runtime.h>
#include <math.h>

#define BB 4
#define NN 2048
#define HH 4
#define DD 128
#define QB 64    // queries per CTA in tensor attention
#define PCKH 24  // fp16 packed-row stride (words)
#define AJW 68   // adjb row stride (words, 16B-aligned)

// ---- device scratch ----
__device__ float g_h[(size_t)BB * HH * NN * DD];          // [b,h,n,o]
__device__ __align__(16) unsigned g_htp[(size_t)BB * HH * 64 * DD * 16]; // fp16 h tiles
__device__ __align__(16) unsigned g_attp[(size_t)BB * NN * 256]; // fp16 concat(att) words
__device__ float g_es[BB * HH * NN];
__device__ float g_es2[BB * HH * NN];
__device__ float g_ed[BB * HH * NN];
__device__ float g_ed2[BB * HH * NN];
__device__ __align__(16) unsigned g_wph[DD][256];         // out_proj_w fp16 [col][word]
__device__ __align__(16) unsigned g_adjb[(size_t)BB * NN * 64]; // adjacency bitmask

// ---- packed fp32x2 helpers ----
#define FMA2(d, a, b, c) \
    asm("fma.rn.f32x2 %0, %1, %2, %3;" : "=l"(d) : "l"(a), "l"(b), "l"(c))
#define PACK2(d, x) \
    asm("mov.b64 %0, {%1, %1};" : "=l"(d) : "r"(__float_as_uint(x)))
__device__ __forceinline__ float lo2(unsigned long long v) {
    return __uint_as_float((unsigned)(v & 0xffffffffull));
}
__device__ __forceinline__ float hi2(unsigned long long v) {
    return __uint_as_float((unsigned)(v >> 32));
}

__device__ __forceinline__ unsigned f2h2(float lo, float hi) {
    unsigned r;
    asm("cvt.rn.f16x2.f32 %0, %1, %2;" : "=r"(r) : "f"(hi), "f"(lo));
    return r;
}

__device__ __forceinline__ void mma_f16(float* c, unsigned a0, unsigned a1,
                                        unsigned a2, unsigned a3,
                                        unsigned b0, unsigned b1) {
    asm volatile(
        "mma.sync.aligned.m16n8k16.row.col.f32.f16.f16.f32 "
        "{%0,%1,%2,%3}, {%4,%5,%6,%7}, {%8,%9}, {%0,%1,%2,%3};"
        : "+f"(c[0]), "+f"(c[1]), "+f"(c[2]), "+f"(c[3])
        : "r"(a0), "r"(a1), "r"(a2), "r"(a3), "r"(b0), "r"(b1));
}

// ============================================================
// Kernel -1: pack adjacency -> bitmask. warp per row.
// ============================================================
__global__ void k_packadj(const int* __restrict__ adj) {
    int wid = threadIdx.x >> 5, lane = threadIdx.x & 31;
    size_t row = (size_t)blockIdx.x * 8 + wid;
    const int4* arow = (const int4*)(adj + row * NN);
    unsigned* dst = g_adjb + row * 64;
#pragma unroll 4
    for (int it = 0; it < 16; it++) {
        int4 v = arow[it * 32 + lane];
        unsigned nib = (v.x != 0 ? 1u : 0u) | (v.y != 0 ? 2u : 0u) |
                       (v.z != 0 ? 4u : 0u) | (v.w != 0 ? 8u : 0u);
        unsigned nv = nib << (4 * (lane & 7));
        nv |= __shfl_xor_sync(0xffffffffu, nv, 1);
        nv |= __shfl_xor_sync(0xffffffffu, nv, 2);
        nv |= __shfl_xor_sync(0xffffffffu, nv, 4);
        if ((lane & 7) == 0) dst[it * 4 + (lane >> 3)] = nv;
    }
}

// ============================================================
// Kernel 0: pack out_proj_w -> fp16 words [col][w], w = k-pair
// ============================================================
__global__ void k_prepw(const float* __restrict__ Wp) {
    int idx = blockIdx.x * 256 + threadIdx.x;  // 32768 total
    int col = idx & 127, w = idx >> 7;
    g_wph[col][w] = f2h2(Wp[(2 * w) * DD + col], Wp[(2 * w + 1) * DD + col]);
}

// ============================================================
// Kernel 1: h = x @ W per head; writes g_h and fp16 tiles g_htp
// ============================================================
__global__ void k_project(const float* __restrict__ x, const float* __restrict__ W) {
    __shared__ __align__(16) float xs_t[DD][20];
    __shared__ float ht_s[DD][17];
    int b = blockIdx.y, n0 = blockIdx.x * 16, tid = threadIdx.x;
#pragma unroll
    for (int i = 0; i < 8; i++) {
        int j = tid + i * 256;
        int r = j >> 7, k = j & 127;
        xs_t[k][r] = x[((size_t)b * NN + n0 + r) * DD + k];
    }
    __syncthreads();
    int col = tid & 127, rs = tid >> 7;
    for (int h = 0; h < HH; h++) {
        const float* Wh = W + h * DD * DD + col;
        unsigned long long acc[4] = {0ull, 0ull, 0ull, 0ull};
#pragma unroll 8
        for (int k = 0; k < DD; k++) {
            unsigned long long wp;
            PACK2(wp, Wh[k * DD]);
            ulonglong2 x01 = *(const ulonglong2*)&xs_t[k][rs * 8];
            ulonglong2 x23 = *(const ulonglong2*)&xs_t[k][rs * 8 + 4];
            FMA2(acc[0], wp, x01.x, acc[0]);
            FMA2(acc[1], wp, x01.y, acc[1]);
            FMA2(acc[2], wp, x23.x, acc[2]);
            FMA2(acc[3], wp, x23.y, acc[3]);
        }
        size_t base = ((size_t)(b * HH + h) * NN + n0 + rs * 8) * DD + col;
#pragma unroll
        for (int p = 0; p < 4; p++) {
            float vlo = lo2(acc[p]), vhi = hi2(acc[p]);
            g_h[base + (size_t)(2 * p) * DD] = vlo;
            g_h[base + (size_t)(2 * p + 1) * DD] = vhi;
            ht_s[col][rs * 8 + 2 * p] = vlo;
            ht_s[col][rs * 8 + 2 * p + 1] = vhi;
        }
        __syncthreads();
        // write fp16 tile words (pair-packed, pslot order within 8-word groups)
        {
            int o = tid >> 1, j0 = (tid & 1) * 8;
            int chunk = n0 >> 5;
            int mbase = (n0 & 31) + j0;   // 8-aligned
            int w0 = mbase >> 1;          // word base (4-aligned)
            unsigned* dst =
                g_htp + (((size_t)(b * HH + h) * 64 + chunk) * DD + o) * 16;
#pragma unroll
            for (int t = 0; t < 4; t++) {
                int w = w0 + t;
                int slot = (w >> 3) * 8 + 2 * (w & 3) + ((w & 7) >> 2);
                dst[slot] = f2h2(ht_s[o][j0 + 2 * t], ht_s[o][j0 + 2 * t + 1]);
            }
        }
        __syncthreads();
    }
}

// ============================================================
// Kernel 2: scores -> 4 exps per (b,h,n)
// ============================================================
__global__ void k_scores(const float* __restrict__ a) {
    int warp = (blockIdx.x * blockDim.x + threadIdx.x) >> 5;
    int lane = threadIdx.x & 31;
    int hidx = (warp / NN) % HH;
    float4 hv = ((const float4*)(g_h + (size_t)warp * DD))[lane];
    float4 av = ((const float4*)(a + hidx * 2 * DD))[lane];
    float4 bv = ((const float4*)(a + hidx * 2 * DD + DD))[lane];
    float s = hv.x * av.x + hv.y * av.y + hv.z * av.z + hv.w * av.w;
    float d = hv.x * bv.x + hv.y * bv.y + hv.z * bv.z + hv.w * bv.w;
#pragma unroll
    for (int off = 16; off; off >>= 1) {
        s += __shfl_down_sync(0xffffffffu, s, off);
        d += __shfl_down_sync(0xffffffffu, d, off);
    }
    if (!lane) {
        g_es[warp] = expf(s);
        g_es2[warp] = expf(0.2f * s);
        g_ed[warp] = expf(d);
        g_ed2[warp] = expf(0.2f * d);
    }
}

// ============================================================
// Kernel 3: fp16 warp-MMA attention, double-buffered, 1 barrier
// per chunk. CTA = (b,h) x 64 queries. Warp tile: 32q x 32o.
// Epilogue writes fp16-packed g_attp (consumed by outproj).
// ============================================================
__global__ void __launch_bounds__(256, 3)
k_attn_mma(float* __restrict__ alpha, int write_alpha) {
    __shared__ __align__(16) float ed_s[NN], ed2_s[NN];        // 16 KB
    __shared__ __align__(16) unsigned adjb[QB][AJW];           // 17.4 KB
    __shared__ __align__(16) unsigned h_pack[2][DD * PCKH];    // 24.6 KB
    __shared__ __align__(16) unsigned w_pack[2][QB * PCKH];    // 12.3 KB
    __shared__ float esr[QB], es2r[QB], izr[QB];

    int b = blockIdx.z, hh = blockIdx.y, q0 = blockIdx.x * QB;
    int bh = b * HH + hh;
    int tid = threadIdx.x, wid = tid >> 5, lane = tid & 31;

    const float* edp = g_ed + bh * NN;
    const float* ed2p = g_ed2 + bh * NN;
    for (int m = tid; m < NN; m += 256) {
        ed_s[m] = edp[m];
        ed2_s[m] = ed2p[m];
    }
    if (tid < QB) {
        int idx = bh * NN + q0 + tid;
        esr[tid] = g_es[idx];
        es2r[tid] = g_es2[idx];
    }
    {
        int r = tid >> 2, j0 = (tid & 3) * 16;
        const uint4* src =
            (const uint4*)(g_adjb + ((size_t)(b * NN + q0 + r)) * 64 + j0);
#pragma unroll
        for (int u = 0; u < 4; u++) *(uint4*)&adjb[r][j0 + u * 4] = src[u];
    }
    __syncthreads();

    // ---- Z per row from bits ----
#pragma unroll
    for (int rr = 0; rr < 8; rr++) {
        int r = wid * 8 + rr;
        float es = esr[r], es2 = es2r[r];
        float z = 0.f;
        for (int j = 0; j < NN / 32; j++) {
            unsigned w = adjb[r][j];
            if ((w >> lane) & 1u) {
                int m = j * 32 + lane;
                z += fmaxf(es * ed_s[m], es2 * ed2_s[m]);
            }
        }
#pragma unroll
        for (int off = 16; off; off >>= 1) z += __shfl_down_sync(0xffffffffu, z, off);
        if (!lane) izr[r] = z;
    }
    __syncthreads();
    if (tid < QB) izr[tid] = 1.0f / izr[tid];
    __syncthreads();

    // ---- pipelined main loop ----
    float acc[2][4][4];
#pragma unroll
    for (int i = 0; i < 2; i++)
#pragma unroll
        for (int j = 0; j < 4; j++)
#pragma unroll
            for (int k = 0; k < 4; k++) acc[i][j][k] = 0.f;

    int o = tid >> 1, half = tid & 1;
    const uint4* hsrc = (const uint4*)(g_htp + ((size_t)bh * 64 * DD + o) * 16);

    int q = tid >> 2, g = tid & 3;
    float* alrow = alpha + ((size_t)bh * NN + q0 + q) * NN;
    float p1 = esr[q] * izr[q], p2 = es2r[q] * izr[q];

    int wq0 = (wid >> 2) * 32, oh = (wid & 3) * 32;
    int frow = lane >> 2, tig = lane & 3, fcol = tig * 2;

    uint4 hreg[2];
    float wv[8];

#define PRODUCE_W(cc)                                                          \
    do {                                                                       \
        int i0 = (cc) * 32 + 2 * g;                                            \
        float2 ea = *(const float2*)&ed_s[i0];                                 \
        float2 eb = *(const float2*)&ed_s[i0 + 8];                             \
        float2 ec = *(const float2*)&ed_s[i0 + 16];                            \
        float2 ed = *(const float2*)&ed_s[i0 + 24];                            \
        float2 fa = *(const float2*)&ed2_s[i0];                                \
        float2 fb = *(const float2*)&ed2_s[i0 + 8];                            \
        float2 fc = *(const float2*)&ed2_s[i0 + 16];                           \
        float2 fd = *(const float2*)&ed2_s[i0 + 24];                           \
        unsigned pb = adjb[q][cc] >> (2 * g);                                  \
        wv[0] = (pb & 0x1u) ? fmaxf(p1 * ea.x, p2 * fa.x) : 0.f;               \
        wv[1] = (pb & 0x2u) ? fmaxf(p1 * ea.y, p2 * fa.y) : 0.f;               \
        wv[2] = (pb & 0x100u) ? fmaxf(p1 * eb.x, p2 * fb.x) : 0.f;             \
        wv[3] = (pb & 0x200u) ? fmaxf(p1 * eb.y, p2 * fb.y) : 0.f;             \
        wv[4] = (pb & 0x10000u) ? fmaxf(p1 * ec.x, p2 * fc.x) : 0.f;           \
        wv[5] = (pb & 0x20000u) ? fmaxf(p1 * ec.y, p2 * fc.y) : 0.f;           \
        wv[6] = (pb & 0x1000000u) ? fmaxf(p1 * ed.x, p2 * fd.x) : 0.f;         \
        wv[7] = (pb & 0x2000000u) ? fmaxf(p1 * ed.y, p2 * fd.y) : 0.f;         \
        if (write_alpha) {                                                     \
            float* ar = alrow + (cc) * 32 + 2 * g;                             \
            *(float2*)ar = make_float2(wv[0], wv[1]);                          \
            *(float2*)(ar + 8) = make_float2(wv[2], wv[3]);                    \
            *(float2*)(ar + 16) = make_float2(wv[4], wv[5]);                   \
            *(float2*)(ar + 24) = make_float2(wv[6], wv[7]);                   \
        }                                                                      \
    } while (0)

    hreg[0] = hsrc[half];
    hreg[1] = hsrc[2 + half];
    PRODUCE_W(0);

    for (int c = 0; c < NN / 32; c++) {
        int buf = c & 1;
        *(uint4*)&h_pack[buf][o * PCKH + 4 * half] = hreg[0];
        *(uint4*)&h_pack[buf][o * PCKH + 8 + 4 * half] = hreg[1];
        {
            uint2 v0, v1;
            v0.x = f2h2(wv[0], wv[1]);
            v0.y = f2h2(wv[2], wv[3]);
            v1.x = f2h2(wv[4], wv[5]);
            v1.y = f2h2(wv[6], wv[7]);
            *(uint2*)&w_pack[buf][q * PCKH + 2 * g] = v0;
            *(uint2*)&w_pack[buf][q * PCKH + 8 + 2 * g] = v1;
        }

        if (c < NN / 32 - 1) {
            int cn = c + 1;
            hreg[0] = hsrc[(size_t)cn * DD * 4 + half];
            hreg[1] = hsrc[(size_t)cn * DD * 4 + 2 + half];
            PRODUCE_W(cn);
        }

        __syncthreads();

#pragma unroll
        for (int ks = 0; ks < 2; ks++) {
            int wcol = ks * 8 + 2 * tig;
            uint2 aA0 = *(const uint2*)&w_pack[buf][(wq0 + frow) * PCKH + wcol];
            uint2 aA1 = *(const uint2*)&w_pack[buf][(wq0 + 8 + frow) * PCKH + wcol];
            uint2 aB0 = *(const uint2*)&w_pack[buf][(wq0 + 16 + frow) * PCKH + wcol];
            uint2 aB1 = *(const uint2*)&w_pack[buf][(wq0 + 24 + frow) * PCKH + wcol];
#pragma unroll
            for (int nt = 0; nt < 4; nt++) {
                uint2 bb =
                    *(const uint2*)&h_pack[buf][(oh + nt * 8 + frow) * PCKH + wcol];
                mma_f16(acc[0][nt], aA0.x, aA1.x, aA0.y, aA1.y, bb.x, bb.y);
                mma_f16(acc[1][nt], aB0.x, aB1.x, aB0.y, aB1.y, bb.x, bb.y);
            }
        }
    }
#undef PRODUCE_W

    // epilogue: write fp16-packed concat words for outproj
#pragma unroll
    for (int qb = 0; qb < 2; qb++)
#pragma unroll
        for (int nt = 0; nt < 4; nt++) {
            int n = q0 + wq0 + qb * 16 + frow;
            int wrd = hh * 64 + ((oh + nt * 8) >> 1) + tig;
            unsigned* p = g_attp + ((size_t)b * NN + n) * 256 + wrd;
            p[0] = f2h2(acc[qb][nt][0], acc[qb][nt][1]);
            p[8 * 256] = f2h2(acc[qb][nt][2], acc[qb][nt][3]);
        }
}

// ============================================================
// Kernel 4: out = concat(att) @ Wp + bias, fp16 warp-MMA.
// CTA: 64 rows x 128 cols, K=512 in 16 chunks. Same skeleton
// as k_attn (PCKH tiles, double buffer, 1 barrier/chunk).
// ============================================================
__global__ void __launch_bounds__(256, 3)
k_outproj_f16(const float* __restrict__ bias, float* __restrict__ out) {
    __shared__ __align__(16) unsigned a_pack[2][QB * PCKH];   // 12.3 KB
    __shared__ __align__(16) unsigned b_pack[2][DD * PCKH];   // 24.6 KB
    __shared__ float bias_s[DD];

    int tid = threadIdx.x, wid = tid >> 5, lane = tid & 31;
    int row0 = blockIdx.x * QB;
    if (tid < DD) bias_s[tid] = bias[tid];
    __syncthreads();

    float acc[2][4][4];
#pragma unroll
    for (int i = 0; i < 2; i++)
#pragma unroll
        for (int j = 0; j < 4; j++)
#pragma unroll
            for (int k = 0; k < 4; k++) acc[i][j][k] = 0.f;

    // a staging: 4 rows x 2 quads per 8-lane phase (conflict-free @ stride 24)
    int a_row = (tid >> 6) * 16 + ((tid >> 1) & 15);
    int a_quad = (tid & 1) + 2 * ((tid >> 5) & 1);
    const uint4* asrc =
        (const uint4*)(g_attp + (size_t)(row0 + a_row) * 256) + a_quad;

    // b staging: same pattern as attn h staging
    int b_col = tid >> 1, b_half = tid & 1;
    const uint4* bsrc = (const uint4*)&g_wph[b_col][0];

    int wq0 = (wid >> 2) * 32, oh = (wid & 3) * 32;
    int frow = lane >> 2, tig = lane & 3, fcol = tig * 2;

    uint4 areg = asrc[0];
    uint4 breg0 = bsrc[b_half];
    uint4 breg1 = bsrc[2 + b_half];

    for (int c = 0; c < 16; c++) {
        int buf = c & 1;
        *(uint4*)&a_pack[buf][a_row * PCKH + a_quad * 4] = areg;
        *(uint4*)&b_pack[buf][b_col * PCKH + 4 * b_half] = breg0;
        *(uint4*)&b_pack[buf][b_col * PCKH + 8 + 4 * b_half] = breg1;

        if (c < 15) {
            areg = asrc[(c + 1) * 4];
            breg0 = bsrc[(c + 1) * 4 + b_half];
            breg1 = bsrc[(c + 1) * 4 + 2 + b_half];
        }
        __syncthreads();

#pragma unroll
        for (int ks = 0; ks < 2; ks++) {
            int wcol = ks * 8 + 2 * tig;
            uint2 aA0 = *(const uint2*)&a_pack[buf][(wq0 + frow) * PCKH + wcol];
            uint2 aA1 = *(const uint2*)&a_pack[buf][(wq0 + 8 + frow) * PCKH + wcol];
            uint2 aB0 = *(const uint2*)&a_pack[buf][(wq0 + 16 + frow) * PCKH + wcol];
            uint2 aB1 = *(const uint2*)&a_pack[buf][(wq0 + 24 + frow) * PCKH + wcol];
#pragma unroll
            for (int nt = 0; nt < 4; nt++) {
                uint2 bb =
                    *(const uint2*)&b_pack[buf][(oh + nt * 8 + frow) * PCKH + wcol];
                mma_f16(acc[0][nt], aA0.x, aA1.x, aA0.y, aA1.y, bb.x, bb.y);
                mma_f16(acc[1][nt], aB0.x, aB1.x, aB0.y, aB1.y, bb.x, bb.y);
            }
        }
    }

    // epilogue: + bias, fp32 out
#pragma unroll
    for (int qb = 0; qb < 2; qb++)
#pragma unroll
        for (int nt = 0; nt < 4; nt++) {
            int rr = row0 + wq0 + qb * 16 + frow;
            int oo = oh + nt * 8 + fcol;
            float b0 = bias_s[oo], b1 = bias_s[oo + 1];
            float* p0 = out + (size_t)rr * DD + oo;
            *(float2*)p0 = make_float2(acc[qb][nt][0] + b0, acc[qb][nt][1] + b1);
            *(float2*)(p0 + (size_t)8 * DD) =
                make_float2(acc[qb][nt][2] + b0, acc[qb][nt][3] + b1);
        }
}

// ============================================================
extern "C" void kernel_launch(void* const* d_in, const int* in_sizes, int n_in,
                              void* d_out, int out_size) {
    const float* x    = (const float*)d_in[0];
    const int*   adj  = (const int*)d_in[1];
    const float* W    = (const float*)d_in[2];
    const float* a    = (const float*)d_in[3];
    const float* Wp   = (const float*)d_in[4];
    const float* bias = (const float*)d_in[5];

    const size_t OUT_E = (size_t)BB * NN * DD;
    const size_t AL_E  = (size_t)BB * HH * NN * NN;

    float* outp = nullptr;
    float* alphap = nullptr;
    int write_alpha = 0, write_out = 0;

    if ((size_t)out_size >= OUT_E + AL_E) {
        outp = (float*)d_out;
        alphap = (float*)d_out + OUT_E;
        write_alpha = 1;
        write_out = 1;
    } else if ((size_t)out_size >= AL_E) {
        alphap = (float*)d_out;
        write_alpha = 1;
    } else {
        outp = (float*)d_out;
        write_out = 1;
    }
    if (!alphap) alphap = g_h;  // dummy, never stored to when !write_alpha

    k_packadj<<<(BB * NN) / 8, 256>>>(adj);
    k_project<<<dim3(NN / 16, BB), 256>>>(x, W);
    k_scores<<<(BB * HH * NN * 32) / 256, 256>>>(a);
    if (write_out) k_prepw<<<128, 256>>>(Wp);
    k_attn_mma<<<dim3(NN / QB, HH, BB), 256>>>(alphap, write_alpha);
    if (write_out)
        k_outproj_f16<<<(BB * NN) / QB, 256>>>(bias, outp);
}

// round 12
// speedup vs baseline: 1.8056x; 1.0447x over previous
#include <cuda_runtime.h>
#include <math.h>

#define BB 4
#define NN 2048
#define HH 4
#define DD 128
#define QB 64    // queries per CTA in tensor attention
#define PCKH 24  // fp16 packed-row stride (words)
#define AJW 68   // adjb row stride (words, 16B-aligned)

// ---- device scratch ----
__device__ float g_h[(size_t)BB * HH * NN * DD];          // [b,h,n,o]
__device__ __align__(16) unsigned g_htp[(size_t)BB * HH * 64 * DD * 16]; // fp16 h tiles (linear words)
__device__ __align__(16) unsigned g_attp[(size_t)BB * NN * 256]; // fp16 concat(att) words
__device__ float g_es[BB * HH * NN];
__device__ float g_es2[BB * HH * NN];
__device__ float g_ed[BB * HH * NN];
__device__ float g_ed2[BB * HH * NN];
__device__ __align__(16) unsigned g_wph[DD][256];         // out_proj_w fp16 [col][word]
__device__ __align__(16) unsigned g_adjb[(size_t)BB * NN * 64]; // adjacency bitmask

// ---- packed fp32x2 helpers ----
#define FMA2(d, a, b, c) \
    asm("fma.rn.f32x2 %0, %1, %2, %3;" : "=l"(d) : "l"(a), "l"(b), "l"(c))
#define PACK2(d, x) \
    asm("mov.b64 %0, {%1, %1};" : "=l"(d) : "r"(__float_as_uint(x)))
__device__ __forceinline__ float lo2(unsigned long long v) {
    return __uint_as_float((unsigned)(v & 0xffffffffull));
}
__device__ __forceinline__ float hi2(unsigned long long v) {
    return __uint_as_float((unsigned)(v >> 32));
}

__device__ __forceinline__ unsigned f2h2(float lo, float hi) {
    unsigned r;
    asm("cvt.rn.f16x2.f32 %0, %1, %2;" : "=r"(r) : "f"(hi), "f"(lo));
    return r;
}

__device__ __forceinline__ void mma_f16(float* c, unsigned a0, unsigned a1,
                                        unsigned a2, unsigned a3,
                                        unsigned b0, unsigned b1) {
    asm volatile(
        "mma.sync.aligned.m16n8k16.row.col.f32.f16.f16.f32 "
        "{%0,%1,%2,%3}, {%4,%5,%6,%7}, {%8,%9}, {%0,%1,%2,%3};"
        : "+f"(c[0]), "+f"(c[1]), "+f"(c[2]), "+f"(c[3])
        : "r"(a0), "r"(a1), "r"(a2), "r"(a3), "r"(b0), "r"(b1));
}

// ============================================================
// Kernel -1: pack adjacency -> bitmask. warp per row.
// ============================================================
__global__ void k_packadj(const int* __restrict__ adj) {
    int wid = threadIdx.x >> 5, lane = threadIdx.x & 31;
    size_t row = (size_t)blockIdx.x * 8 + wid;
    const int4* arow = (const int4*)(adj + row * NN);
    unsigned* dst = g_adjb + row * 64;
#pragma unroll 4
    for (int it = 0; it < 16; it++) {
        int4 v = arow[it * 32 + lane];
        unsigned nib = (v.x != 0 ? 1u : 0u) | (v.y != 0 ? 2u : 0u) |
                       (v.z != 0 ? 4u : 0u) | (v.w != 0 ? 8u : 0u);
        unsigned nv = nib << (4 * (lane & 7));
        nv |= __shfl_xor_sync(0xffffffffu, nv, 1);
        nv |= __shfl_xor_sync(0xffffffffu, nv, 2);
        nv |= __shfl_xor_sync(0xffffffffu, nv, 4);
        if ((lane & 7) == 0) dst[it * 4 + (lane >> 3)] = nv;
    }
}

// ============================================================
// Kernel 0: pack out_proj_w -> fp16 words [col][w], w = k-pair
// ============================================================
__global__ void k_prepw(const float* __restrict__ Wp) {
    int idx = blockIdx.x * 256 + threadIdx.x;  // 32768 total
    int col = idx & 127, w = idx >> 7;
    g_wph[col][w] = f2h2(Wp[(2 * w) * DD + col], Wp[(2 * w + 1) * DD + col]);
}

// ============================================================
// Kernel 1: h = x @ W per head; writes g_h and fp16 tiles g_htp
// ============================================================
__global__ void k_project(const float* __restrict__ x, const float* __restrict__ W) {
    __shared__ __align__(16) float xs_t[DD][20];
    __shared__ float ht_s[DD][17];
    int b = blockIdx.y, n0 = blockIdx.x * 16, tid = threadIdx.x;
#pragma unroll
    for (int i = 0; i < 8; i++) {
        int j = tid + i * 256;
        int r = j >> 7, k = j & 127;
        xs_t[k][r] = x[((size_t)b * NN + n0 + r) * DD + k];
    }
    __syncthreads();
    int col = tid & 127, rs = tid >> 7;
    for (int h = 0; h < HH; h++) {
        const float* Wh = W + h * DD * DD + col;
        unsigned long long acc[4] = {0ull, 0ull, 0ull, 0ull};
#pragma unroll 8
        for (int k = 0; k < DD; k++) {
            unsigned long long wp;
            PACK2(wp, Wh[k * DD]);
            ulonglong2 x01 = *(const ulonglong2*)&xs_t[k][rs * 8];
            ulonglong2 x23 = *(const ulonglong2*)&xs_t[k][rs * 8 + 4];
            FMA2(acc[0], wp, x01.x, acc[0]);
            FMA2(acc[1], wp, x01.y, acc[1]);
            FMA2(acc[2], wp, x23.x, acc[2]);
            FMA2(acc[3], wp, x23.y, acc[3]);
        }
        size_t base = ((size_t)(b * HH + h) * NN + n0 + rs * 8) * DD + col;
#pragma unroll
        for (int p = 0; p < 4; p++) {
            float vlo = lo2(acc[p]), vhi = hi2(acc[p]);
            g_h[base + (size_t)(2 * p) * DD] = vlo;
            g_h[base + (size_t)(2 * p + 1) * DD] = vhi;
            ht_s[col][rs * 8 + 2 * p] = vlo;
            ht_s[col][rs * 8 + 2 * p + 1] = vhi;
        }
        __syncthreads();
        // write fp16 tile words (LINEAR: word w = m-pair (2w, 2w+1))
        {
            int o = tid >> 1, j0 = (tid & 1) * 8;
            int chunk = n0 >> 5;
            int w0 = ((n0 & 31) + j0) >> 1;  // 4-aligned word base
            unsigned* dst =
                g_htp + (((size_t)(b * HH + h) * 64 + chunk) * DD + o) * 16 + w0;
#pragma unroll
            for (int t = 0; t < 4; t++)
                dst[t] = f2h2(ht_s[o][j0 + 2 * t], ht_s[o][j0 + 2 * t + 1]);
        }
        __syncthreads();
    }
}

// ============================================================
// Kernel 2: scores -> 4 exps per (b,h,n)
// ============================================================
__global__ void k_scores(const float* __restrict__ a) {
    int warp = (blockIdx.x * blockDim.x + threadIdx.x) >> 5;
    int lane = threadIdx.x & 31;
    int hidx = (warp / NN) % HH;
    float4 hv = ((const float4*)(g_h + (size_t)warp * DD))[lane];
    float4 av = ((const float4*)(a + hidx * 2 * DD))[lane];
    float4 bv = ((const float4*)(a + hidx * 2 * DD + DD))[lane];
    float s = hv.x * av.x + hv.y * av.y + hv.z * av.z + hv.w * av.w;
    float d = hv.x * bv.x + hv.y * bv.y + hv.z * bv.z + hv.w * bv.w;
#pragma unroll
    for (int off = 16; off; off >>= 1) {
        s += __shfl_down_sync(0xffffffffu, s, off);
        d += __shfl_down_sync(0xffffffffu, d, off);
    }
    if (!lane) {
        g_es[warp] = expf(s);
        g_es2[warp] = expf(0.2f * s);
        g_ed[warp] = expf(d);
        g_ed2[warp] = expf(0.2f * d);
    }
}

// ============================================================
// Kernel 3: fp16 warp-MMA attention, double-buffered, 1 barrier
// per chunk, producer math after MMA. CTA = (b,h) x 64 queries.
// ============================================================
__global__ void __launch_bounds__(256, 3)
k_attn_mma(float* __restrict__ alpha, int write_alpha) {
    __shared__ __align__(16) float ed_s[NN], ed2_s[NN];        // 16 KB
    __shared__ __align__(16) unsigned adjb[QB][AJW];           // 17.4 KB
    __shared__ __align__(16) unsigned h_pack[2][DD * PCKH];    // 24.6 KB
    __shared__ __align__(16) unsigned w_pack[2][QB * PCKH];    // 12.3 KB
    __shared__ float esr[QB], es2r[QB], izr[QB];

    int b = blockIdx.z, hh = blockIdx.y, q0 = blockIdx.x * QB;
    int bh = b * HH + hh;
    int tid = threadIdx.x, wid = tid >> 5, lane = tid & 31;

    const float* edp = g_ed + bh * NN;
    const float* ed2p = g_ed2 + bh * NN;
    for (int m = tid; m < NN; m += 256) {
        ed_s[m] = edp[m];
        ed2_s[m] = ed2p[m];
    }
    if (tid < QB) {
        int idx = bh * NN + q0 + tid;
        esr[tid] = g_es[idx];
        es2r[tid] = g_es2[idx];
    }
    {
        int r = tid >> 2, j0 = (tid & 3) * 16;
        const uint4* src =
            (const uint4*)(g_adjb + ((size_t)(b * NN + q0 + r)) * 64 + j0);
#pragma unroll
        for (int u = 0; u < 4; u++) *(uint4*)&adjb[r][j0 + u * 4] = src[u];
    }
    __syncthreads();

    // ---- Z per row from bits ----
#pragma unroll
    for (int rr = 0; rr < 8; rr++) {
        int r = wid * 8 + rr;
        float es = esr[r], es2 = es2r[r];
        float z = 0.f;
        for (int j = 0; j < NN / 32; j++) {
            unsigned w = adjb[r][j];
            if ((w >> lane) & 1u) {
                int m = j * 32 + lane;
                z += fmaxf(es * ed_s[m], es2 * ed2_s[m]);
            }
        }
#pragma unroll
        for (int off = 16; off; off >>= 1) z += __shfl_down_sync(0xffffffffu, z, off);
        if (!lane) izr[r] = z;
    }
    __syncthreads();
    if (tid < QB) izr[tid] = 1.0f / izr[tid];
    __syncthreads();

    // ---- pipelined main loop ----
    float acc[2][4][4];
#pragma unroll
    for (int i = 0; i < 2; i++)
#pragma unroll
        for (int j = 0; j < 4; j++)
#pragma unroll
            for (int k = 0; k < 4; k++) acc[i][j][k] = 0.f;

    // h staging: thread owns row o, words 8*half .. 8*half+7 (linear)
    int o = tid >> 1, half = tid & 1;
    const uint4* hsrc = (const uint4*)(g_htp + ((size_t)bh * 64 * DD + o) * 16);

    // w producer: thread (q = tid>>2, g = tid&3) handles m = 32c + 8g .. +7
    int q = tid >> 2, g = tid & 3;
    float* alrow = alpha + ((size_t)bh * NN + q0 + q) * NN;
    float p1 = esr[q] * izr[q], p2 = es2r[q] * izr[q];

    int wq0 = (wid >> 2) * 32, oh = (wid & 3) * 32;
    int frow = lane >> 2, tig = lane & 3, fcol = tig * 2;

    uint4 hreg[2];
    unsigned wpk[4];

#define PRODUCE_W(cc)                                                          \
    do {                                                                       \
        int m0 = (cc) * 32 + 8 * g;                                            \
        float4 e0 = *(const float4*)&ed_s[m0];                                 \
        float4 e1 = *(const float4*)&ed_s[m0 + 4];                             \
        float4 f0 = *(const float4*)&ed2_s[m0];                                \
        float4 f1 = *(const float4*)&ed2_s[m0 + 4];                            \
        unsigned pb = adjb[q][cc] >> (8 * g);                                  \
        float wv0 = (pb & 1u) ? fmaxf(p1 * e0.x, p2 * f0.x) : 0.f;             \
        float wv1 = (pb & 2u) ? fmaxf(p1 * e0.y, p2 * f0.y) : 0.f;             \
        float wv2 = (pb & 4u) ? fmaxf(p1 * e0.z, p2 * f0.z) : 0.f;             \
        float wv3 = (pb & 8u) ? fmaxf(p1 * e0.w, p2 * f0.w) : 0.f;             \
        float wv4 = (pb & 16u) ? fmaxf(p1 * e1.x, p2 * f1.x) : 0.f;            \
        float wv5 = (pb & 32u) ? fmaxf(p1 * e1.y, p2 * f1.y) : 0.f;            \
        float wv6 = (pb & 64u) ? fmaxf(p1 * e1.z, p2 * f1.z) : 0.f;            \
        float wv7 = (pb & 128u) ? fmaxf(p1 * e1.w, p2 * f1.w) : 0.f;           \
        if (write_alpha) {                                                     \
            *(float4*)(alrow + m0) = make_float4(wv0, wv1, wv2, wv3);          \
            *(float4*)(alrow + m0 + 4) = make_float4(wv4, wv5, wv6, wv7);      \
        }                                                                      \
        wpk[0] = f2h2(wv0, wv1);                                               \
        wpk[1] = f2h2(wv2, wv3);                                               \
        wpk[2] = f2h2(wv4, wv5);                                               \
        wpk[3] = f2h2(wv6, wv7);                                               \
    } while (0)

    // prologue: chunk 0
    hreg[0] = hsrc[2 * half];
    hreg[1] = hsrc[2 * half + 1];
    PRODUCE_W(0);

    for (int c = 0; c < NN / 32; c++) {
        int buf = c & 1;
        // stage chunk c (linear slots)
        *(uint4*)&h_pack[buf][o * PCKH + 8 * half] = hreg[0];
        *(uint4*)&h_pack[buf][o * PCKH + 8 * half + 4] = hreg[1];
        *(uint4*)&w_pack[buf][q * PCKH + 4 * g] =
            make_uint4(wpk[0], wpk[1], wpk[2], wpk[3]);

        // prefetch chunk c+1 h (LDG only — latency hidden by barrier+MMA)
        if (c < NN / 32 - 1) {
            hreg[0] = hsrc[(size_t)(c + 1) * DD * 4 + 2 * half];
            hreg[1] = hsrc[(size_t)(c + 1) * DD * 4 + 2 * half + 1];
        }

        __syncthreads();  // chunk c staged

        // MMA: 32q x 32o x 32m per warp (fp16, k16)
#pragma unroll
        for (int ks = 0; ks < 2; ks++) {
            int wcol = ks * 8 + 2 * tig;
            uint2 aA0 = *(const uint2*)&w_pack[buf][(wq0 + frow) * PCKH + wcol];
            uint2 aA1 = *(const uint2*)&w_pack[buf][(wq0 + 8 + frow) * PCKH + wcol];
            uint2 aB0 = *(const uint2*)&w_pack[buf][(wq0 + 16 + frow) * PCKH + wcol];
            uint2 aB1 = *(const uint2*)&w_pack[buf][(wq0 + 24 + frow) * PCKH + wcol];
#pragma unroll
            for (int nt = 0; nt < 4; nt++) {
                uint2 bb =
                    *(const uint2*)&h_pack[buf][(oh + nt * 8 + frow) * PCKH + wcol];
                mma_f16(acc[0][nt], aA0.x, aA1.x, aA0.y, aA1.y, bb.x, bb.y);
                mma_f16(acc[1][nt], aB0.x, aB1.x, aB0.y, aB1.y, bb.x, bb.y);
            }
        }

        // producer math for chunk c+1 (after MMA, before next barrier)
        if (c < NN / 32 - 1) PRODUCE_W(c + 1);
    }
#undef PRODUCE_W

    // epilogue: write fp16-packed concat words for outproj
#pragma unroll
    for (int qb = 0; qb < 2; qb++)
#pragma unroll
        for (int nt = 0; nt < 4; nt++) {
            int n = q0 + wq0 + qb * 16 + frow;
            int wrd = hh * 64 + ((oh + nt * 8) >> 1) + tig;
            unsigned* p = g_attp + ((size_t)b * NN + n) * 256 + wrd;
            p[0] = f2h2(acc[qb][nt][0], acc[qb][nt][1]);
            p[8 * 256] = f2h2(acc[qb][nt][2], acc[qb][nt][3]);
        }
}

// ============================================================
// Kernel 4: out = concat(att) @ Wp + bias, fp16 warp-MMA.
// ============================================================
__global__ void __launch_bounds__(256, 3)
k_outproj_f16(const float* __restrict__ bias, float* __restrict__ out) {
    __shared__ __align__(16) unsigned a_pack[2][QB * PCKH];   // 12.3 KB
    __shared__ __align__(16) unsigned b_pack[2][DD * PCKH];   // 24.6 KB
    __shared__ float bias_s[DD];

    int tid = threadIdx.x, wid = tid >> 5, lane = tid & 31;
    int row0 = blockIdx.x * QB;
    if (tid < DD) bias_s[tid] = bias[tid];
    __syncthreads();

    float acc[2][4][4];
#pragma unroll
    for (int i = 0; i < 2; i++)
#pragma unroll
        for (int j = 0; j < 4; j++)
#pragma unroll
            for (int k = 0; k < 4; k++) acc[i][j][k] = 0.f;

    int a_row = (tid >> 6) * 16 + ((tid >> 1) & 15);
    int a_quad = (tid & 1) + 2 * ((tid >> 5) & 1);
    const uint4* asrc =
        (const uint4*)(g_attp + (size_t)(row0 + a_row) * 256) + a_quad;

    int b_col = tid >> 1, b_half = tid & 1;
    const uint4* bsrc = (const uint4*)&g_wph[b_col][0];

    int wq0 = (wid >> 2) * 32, oh = (wid & 3) * 32;
    int frow = lane >> 2, tig = lane & 3, fcol = tig * 2;

    uint4 areg = asrc[0];
    uint4 breg0 = bsrc[b_half];
    uint4 breg1 = bsrc[2 + b_half];

    for (int c = 0; c < 16; c++) {
        int buf = c & 1;
        *(uint4*)&a_pack[buf][a_row * PCKH + a_quad * 4] = areg;
        *(uint4*)&b_pack[buf][b_col * PCKH + 4 * b_half] = breg0;
        *(uint4*)&b_pack[buf][b_col * PCKH + 8 + 4 * b_half] = breg1;

        if (c < 15) {
            areg = asrc[(c + 1) * 4];
            breg0 = bsrc[(c + 1) * 4 + b_half];
            breg1 = bsrc[(c + 1) * 4 + 2 + b_half];
        }
        __syncthreads();

#pragma unroll
        for (int ks = 0; ks < 2; ks++) {
            int wcol = ks * 8 + 2 * tig;
            uint2 aA0 = *(const uint2*)&a_pack[buf][(wq0 + frow) * PCKH + wcol];
            uint2 aA1 = *(const uint2*)&a_pack[buf][(wq0 + 8 + frow) * PCKH + wcol];
            uint2 aB0 = *(const uint2*)&a_pack[buf][(wq0 + 16 + frow) * PCKH + wcol];
            uint2 aB1 = *(const uint2*)&a_pack[buf][(wq0 + 24 + frow) * PCKH + wcol];
#pragma unroll
            for (int nt = 0; nt < 4; nt++) {
                uint2 bb =
                    *(const uint2*)&b_pack[buf][(oh + nt * 8 + frow) * PCKH + wcol];
                mma_f16(acc[0][nt], aA0.x, aA1.x, aA0.y, aA1.y, bb.x, bb.y);
                mma_f16(acc[1][nt], aB0.x, aB1.x, aB0.y, aB1.y, bb.x, bb.y);
            }
        }
    }

#pragma unroll
    for (int qb = 0; qb < 2; qb++)
#pragma unroll
        for (int nt = 0; nt < 4; nt++) {
            int rr = row0 + wq0 + qb * 16 + frow;
            int oo = oh + nt * 8 + fcol;
            float b0 = bias_s[oo], b1 = bias_s[oo + 1];
            float* p0 = out + (size_t)rr * DD + oo;
            *(float2*)p0 = make_float2(acc[qb][nt][0] + b0, acc[qb][nt][1] + b1);
            *(float2*)(p0 + (size_t)8 * DD) =
                make_float2(acc[qb][nt][2] + b0, acc[qb][nt][3] + b1);
        }
}

// ============================================================
extern "C" void kernel_launch(void* const* d_in, const int* in_sizes, int n_in,
                              void* d_out, int out_size) {
    const float* x    = (const float*)d_in[0];
    const int*   adj  = (const int*)d_in[1];
    const float* W    = (const float*)d_in[2];
    const float* a    = (const float*)d_in[3];
    const float* Wp   = (const float*)d_in[4];
    const float* bias = (const float*)d_in[5];

    const size_t OUT_E = (size_t)BB * NN * DD;
    const size_t AL_E  = (size_t)BB * HH * NN * NN;

    float* outp = nullptr;
    float* alphap = nullptr;
    int write_alpha = 0, write_out = 0;

    if ((size_t)out_size >= OUT_E + AL_E) {
        outp = (float*)d_out;
        alphap = (float*)d_out + OUT_E;
        write_alpha = 1;
        write_out = 1;
    } else if ((size_t)out_size >= AL_E) {
        alphap = (float*)d_out;
        write_alpha = 1;
    } else {
        outp = (float*)d_out;
        write_out = 1;
    }
    if (!alphap) alphap = g_h;  // dummy, never stored to when !write_alpha

    // k_attn is launch #4 so ncu (-s based) profiles it
    k_packadj<<<(BB * NN) / 8, 256>>>(adj);
    k_project<<<dim3(NN / 16, BB), 256>>>(x, W);
    k_scores<<<(BB * HH * NN * 32) / 256, 256>>>(a);
    k_attn_mma<<<dim3(NN / QB, HH, BB), 256>>>(alphap, write_alpha);
    if (write_out) {
        k_prepw<<<128, 256>>>(Wp);
        k_outproj_f16<<<(BB * NN) / QB, 256>>>(bias, outp);
    }
}

// round 13
// speedup vs baseline: 1.8588x; 1.0295x over previous
#include <cuda_runtime.h>
#include <math.h>

#define BB 4
#define NN 2048
#define HH 4
#define DD 128
#define QB 128   // queries per CTA in tensor attention
#define QBO 64   // rows per CTA in outproj
#define PCKH 24  // fp16 packed-row stride (words)
#define AJW 68   // adjb row stride (words, 16B-aligned)

// ---- device scratch ----
__device__ float g_h[(size_t)BB * HH * NN * DD];          // [b,h,n,o]
__device__ __align__(16) unsigned g_htp[(size_t)BB * HH * 64 * DD * 16]; // fp16 h tiles (linear words)
__device__ __align__(16) unsigned g_attp[(size_t)BB * NN * 256]; // fp16 concat(att) words
__device__ float g_es[BB * HH * NN];
__device__ float g_es2[BB * HH * NN];
__device__ float g_ed[BB * HH * NN];
__device__ float g_ed2[BB * HH * NN];
__device__ __align__(16) unsigned g_wph[DD][256];         // out_proj_w fp16 [col][word]
__device__ __align__(16) unsigned g_adjb[(size_t)BB * NN * 64]; // adjacency bitmask

// ---- packed fp32x2 helpers ----
#define FMA2(d, a, b, c) \
    asm("fma.rn.f32x2 %0, %1, %2, %3;" : "=l"(d) : "l"(a), "l"(b), "l"(c))
#define PACK2(d, x) \
    asm("mov.b64 %0, {%1, %1};" : "=l"(d) : "r"(__float_as_uint(x)))
__device__ __forceinline__ float lo2(unsigned long long v) {
    return __uint_as_float((unsigned)(v & 0xffffffffull));
}
__device__ __forceinline__ float hi2(unsigned long long v) {
    return __uint_as_float((unsigned)(v >> 32));
}

__device__ __forceinline__ unsigned f2h2(float lo, float hi) {
    unsigned r;
    asm("cvt.rn.f16x2.f32 %0, %1, %2;" : "=r"(r) : "f"(hi), "f"(lo));
    return r;
}

__device__ __forceinline__ void mma_f16(float* c, unsigned a0, unsigned a1,
                                        unsigned a2, unsigned a3,
                                        unsigned b0, unsigned b1) {
    asm volatile(
        "mma.sync.aligned.m16n8k16.row.col.f32.f16.f16.f32 "
        "{%0,%1,%2,%3}, {%4,%5,%6,%7}, {%8,%9}, {%0,%1,%2,%3};"
        : "+f"(c[0]), "+f"(c[1]), "+f"(c[2]), "+f"(c[3])
        : "r"(a0), "r"(a1), "r"(a2), "r"(a3), "r"(b0), "r"(b1));
}

// ============================================================
// Kernel -1: pack adjacency -> bitmask. warp per row.
// ============================================================
__global__ void k_packadj(const int* __restrict__ adj) {
    int wid = threadIdx.x >> 5, lane = threadIdx.x & 31;
    size_t row = (size_t)blockIdx.x * 8 + wid;
    const int4* arow = (const int4*)(adj + row * NN);
    unsigned* dst = g_adjb + row * 64;
#pragma unroll 4
    for (int it = 0; it < 16; it++) {
        int4 v = arow[it * 32 + lane];
        unsigned nib = (v.x != 0 ? 1u : 0u) | (v.y != 0 ? 2u : 0u) |
                       (v.z != 0 ? 4u : 0u) | (v.w != 0 ? 8u : 0u);
        unsigned nv = nib << (4 * (lane & 7));
        nv |= __shfl_xor_sync(0xffffffffu, nv, 1);
        nv |= __shfl_xor_sync(0xffffffffu, nv, 2);
        nv |= __shfl_xor_sync(0xffffffffu, nv, 4);
        if ((lane & 7) == 0) dst[it * 4 + (lane >> 3)] = nv;
    }
}

// ============================================================
// Kernel 0: pack out_proj_w -> fp16 words [col][w], w = k-pair
// ============================================================
__global__ void k_prepw(const float* __restrict__ Wp) {
    int idx = blockIdx.x * 256 + threadIdx.x;  // 32768 total
    int col = idx & 127, w = idx >> 7;
    g_wph[col][w] = f2h2(Wp[(2 * w) * DD + col], Wp[(2 * w + 1) * DD + col]);
}

// ============================================================
// Kernel 1: h = x @ W per head; writes g_h and fp16 tiles g_htp
// ============================================================
__global__ void k_project(const float* __restrict__ x, const float* __restrict__ W) {
    __shared__ __align__(16) float xs_t[DD][20];
    __shared__ float ht_s[DD][17];
    int b = blockIdx.y, n0 = blockIdx.x * 16, tid = threadIdx.x;
#pragma unroll
    for (int i = 0; i < 8; i++) {
        int j = tid + i * 256;
        int r = j >> 7, k = j & 127;
        xs_t[k][r] = x[((size_t)b * NN + n0 + r) * DD + k];
    }
    __syncthreads();
    int col = tid & 127, rs = tid >> 7;
    for (int h = 0; h < HH; h++) {
        const float* Wh = W + h * DD * DD + col;
        unsigned long long acc[4] = {0ull, 0ull, 0ull, 0ull};
#pragma unroll 8
        for (int k = 0; k < DD; k++) {
            unsigned long long wp;
            PACK2(wp, Wh[k * DD]);
            ulonglong2 x01 = *(const ulonglong2*)&xs_t[k][rs * 8];
            ulonglong2 x23 = *(const ulonglong2*)&xs_t[k][rs * 8 + 4];
            FMA2(acc[0], wp, x01.x, acc[0]);
            FMA2(acc[1], wp, x01.y, acc[1]);
            FMA2(acc[2], wp, x23.x, acc[2]);
            FMA2(acc[3], wp, x23.y, acc[3]);
        }
        size_t base = ((size_t)(b * HH + h) * NN + n0 + rs * 8) * DD + col;
#pragma unroll
        for (int p = 0; p < 4; p++) {
            float vlo = lo2(acc[p]), vhi = hi2(acc[p]);
            g_h[base + (size_t)(2 * p) * DD] = vlo;
            g_h[base + (size_t)(2 * p + 1) * DD] = vhi;
            ht_s[col][rs * 8 + 2 * p] = vlo;
            ht_s[col][rs * 8 + 2 * p + 1] = vhi;
        }
        __syncthreads();
        // write fp16 tile words (LINEAR: word w = m-pair (2w, 2w+1))
        {
            int o = tid >> 1, j0 = (tid & 1) * 8;
            int chunk = n0 >> 5;
            int w0 = ((n0 & 31) + j0) >> 1;  // 4-aligned word base
            unsigned* dst =
                g_htp + (((size_t)(b * HH + h) * 64 + chunk) * DD + o) * 16 + w0;
#pragma unroll
            for (int t = 0; t < 4; t++)
                dst[t] = f2h2(ht_s[o][j0 + 2 * t], ht_s[o][j0 + 2 * t + 1]);
        }
        __syncthreads();
    }
}

// ============================================================
// Kernel 2: scores -> 4 exps per (b,h,n)
// ============================================================
__global__ void k_scores(const float* __restrict__ a) {
    int warp = (blockIdx.x * blockDim.x + threadIdx.x) >> 5;
    int lane = threadIdx.x & 31;
    int hidx = (warp / NN) % HH;
    float4 hv = ((const float4*)(g_h + (size_t)warp * DD))[lane];
    float4 av = ((const float4*)(a + hidx * 2 * DD))[lane];
    float4 bv = ((const float4*)(a + hidx * 2 * DD + DD))[lane];
    float s = hv.x * av.x + hv.y * av.y + hv.z * av.z + hv.w * av.w;
    float d = hv.x * bv.x + hv.y * bv.y + hv.z * bv.z + hv.w * bv.w;
#pragma unroll
    for (int off = 16; off; off >>= 1) {
        s += __shfl_down_sync(0xffffffffu, s, off);
        d += __shfl_down_sync(0xffffffffu, d, off);
    }
    if (!lane) {
        g_es[warp] = expf(s);
        g_es2[warp] = expf(0.2f * s);
        g_ed[warp] = expf(d);
        g_ed2[warp] = expf(0.2f * d);
    }
}

// ============================================================
// Kernel 3: fp16 warp-MMA attention. CTA = (b,h) x 128 queries,
// warp tile 32q x 64o (B fragments reused 2x). Double-buffered,
// 1 barrier/chunk, producer math after MMA.
// ============================================================
__global__ void __launch_bounds__(256, 2)
k_attn_mma(float* __restrict__ alpha, int write_alpha) {
    __shared__ __align__(16) float ed_s[NN], ed2_s[NN];        // 16 KB
    __shared__ __align__(16) unsigned adjb[QB][AJW];           // 34.8 KB
    __shared__ __align__(16) unsigned h_pack[2][DD * PCKH];    // 24.6 KB
    __shared__ __align__(16) unsigned w_pack[2][QB * PCKH];    // 24.6 KB
    __shared__ float esr[QB], es2r[QB], izr[QB];

    int b = blockIdx.z, hh = blockIdx.y, q0 = blockIdx.x * QB;
    int bh = b * HH + hh;
    int tid = threadIdx.x, wid = tid >> 5, lane = tid & 31;

    const float* edp = g_ed + bh * NN;
    const float* ed2p = g_ed2 + bh * NN;
    for (int m = tid; m < NN; m += 256) {
        ed_s[m] = edp[m];
        ed2_s[m] = ed2p[m];
    }
    if (tid < QB) {
        int idx = bh * NN + q0 + tid;
        esr[tid] = g_es[idx];
        es2r[tid] = g_es2[idx];
    }
    // adjacency bitmasks: row r = tid>>1, 32 words each
    {
        int r = tid >> 1, j0 = (tid & 1) * 32;
        const uint4* src =
            (const uint4*)(g_adjb + ((size_t)(b * NN + q0 + r)) * 64 + j0);
#pragma unroll
        for (int u = 0; u < 8; u++) *(uint4*)&adjb[r][j0 + u * 4] = src[u];
    }
    __syncthreads();

    // ---- Z per row from bits (16 rows per warp) ----
#pragma unroll
    for (int rr = 0; rr < 16; rr++) {
        int r = wid * 16 + rr;
        float es = esr[r], es2 = es2r[r];
        float z = 0.f;
        for (int j = 0; j < NN / 32; j++) {
            unsigned w = adjb[r][j];
            if ((w >> lane) & 1u) {
                int m = j * 32 + lane;
                z += fmaxf(es * ed_s[m], es2 * ed2_s[m]);
            }
        }
#pragma unroll
        for (int off = 16; off; off >>= 1) z += __shfl_down_sync(0xffffffffu, z, off);
        if (!lane) izr[r] = z;
    }
    __syncthreads();
    if (tid < QB) izr[tid] = 1.0f / izr[tid];
    __syncthreads();

    // ---- pipelined main loop ----
    float acc[2][8][4];
#pragma unroll
    for (int i = 0; i < 2; i++)
#pragma unroll
        for (int j = 0; j < 8; j++)
#pragma unroll
            for (int k = 0; k < 4; k++) acc[i][j][k] = 0.f;

    // h staging: thread owns row o, words 8*half .. 8*half+7 (linear)
    int o = tid >> 1, half = tid & 1;
    const uint4* hsrc = (const uint4*)(g_htp + ((size_t)bh * 64 * DD + o) * 16);

    // w producer: thread (q = tid>>1, g2 = tid&1) handles m = 32c + 16g2 .. +15
    int q = tid >> 1, g2 = tid & 1;
    float* alrow = alpha + ((size_t)bh * NN + q0 + q) * NN;
    float p1 = esr[q] * izr[q], p2 = es2r[q] * izr[q];

    // warp tile: 32q x 64o
    int wq0 = (wid >> 1) * 32, oh = (wid & 1) * 64;
    int frow = lane >> 2, tig = lane & 3, fcol = tig * 2;

    uint4 hreg[2];
    unsigned wpk[8];

#define PRODUCE_W(cc)                                                          \
    do {                                                                       \
        int m0 = (cc) * 32 + 16 * g2;                                          \
        unsigned pb = adjb[q][cc] >> (16 * g2);                                \
        {                                                                      \
            float4 e0 = *(const float4*)&ed_s[m0];                             \
            float4 e1 = *(const float4*)&ed_s[m0 + 4];                         \
            float4 f0 = *(const float4*)&ed2_s[m0];                            \
            float4 f1 = *(const float4*)&ed2_s[m0 + 4];                        \
            float w0 = (pb & 1u) ? fmaxf(p1 * e0.x, p2 * f0.x) : 0.f;          \
            float w1 = (pb & 2u) ? fmaxf(p1 * e0.y, p2 * f0.y) : 0.f;          \
            float w2 = (pb & 4u) ? fmaxf(p1 * e0.z, p2 * f0.z) : 0.f;          \
            float w3 = (pb & 8u) ? fmaxf(p1 * e0.w, p2 * f0.w) : 0.f;          \
            float w4 = (pb & 16u) ? fmaxf(p1 * e1.x, p2 * f1.x) : 0.f;         \
            float w5 = (pb & 32u) ? fmaxf(p1 * e1.y, p2 * f1.y) : 0.f;         \
            float w6 = (pb & 64u) ? fmaxf(p1 * e1.z, p2 * f1.z) : 0.f;         \
            float w7 = (pb & 128u) ? fmaxf(p1 * e1.w, p2 * f1.w) : 0.f;        \
            if (write_alpha) {                                                 \
                *(float4*)(alrow + m0) = make_float4(w0, w1, w2, w3);          \
                *(float4*)(alrow + m0 + 4) = make_float4(w4, w5, w6, w7);      \
            }                                                                  \
            wpk[0] = f2h2(w0, w1); wpk[1] = f2h2(w2, w3);                      \
            wpk[2] = f2h2(w4, w5); wpk[3] = f2h2(w6, w7);                      \
        }                                                                      \
        {                                                                      \
            float4 e0 = *(const float4*)&ed_s[m0 + 8];                         \
            float4 e1 = *(const float4*)&ed_s[m0 + 12];                        \
            float4 f0 = *(const float4*)&ed2_s[m0 + 8];                        \
            float4 f1 = *(const float4*)&ed2_s[m0 + 12];                       \
            unsigned pc = pb >> 8;                                             \
            float w0 = (pc & 1u) ? fmaxf(p1 * e0.x, p2 * f0.x) : 0.f;          \
            float w1 = (pc & 2u) ? fmaxf(p1 * e0.y, p2 * f0.y) : 0.f;          \
            float w2 = (pc & 4u) ? fmaxf(p1 * e0.z, p2 * f0.z) : 0.f;          \
            float w3 = (pc & 8u) ? fmaxf(p1 * e0.w, p2 * f0.w) : 0.f;          \
            float w4 = (pc & 16u) ? fmaxf(p1 * e1.x, p2 * f1.x) : 0.f;         \
            float w5 = (pc & 32u) ? fmaxf(p1 * e1.y, p2 * f1.y) : 0.f;         \
            float w6 = (pc & 64u) ? fmaxf(p1 * e1.z, p2 * f1.z) : 0.f;         \
            float w7 = (pc & 128u) ? fmaxf(p1 * e1.w, p2 * f1.w) : 0.f;        \
            if (write_alpha) {                                                 \
                *(float4*)(alrow + m0 + 8) = make_float4(w0, w1, w2, w3);      \
                *(float4*)(alrow + m0 + 12) = make_float4(w4, w5, w6, w7);     \
            }                                                                  \
            wpk[4] = f2h2(w0, w1); wpk[5] = f2h2(w2, w3);                      \
            wpk[6] = f2h2(w4, w5); wpk[7] = f2h2(w6, w7);                      \
        }                                                                      \
    } while (0)

    // prologue: chunk 0
    hreg[0] = hsrc[2 * half];
    hreg[1] = hsrc[2 * half + 1];
    PRODUCE_W(0);

    for (int c = 0; c < NN / 32; c++) {
        int buf = c & 1;
        // stage chunk c (linear slots)
        *(uint4*)&h_pack[buf][o * PCKH + 8 * half] = hreg[0];
        *(uint4*)&h_pack[buf][o * PCKH + 8 * half + 4] = hreg[1];
        *(uint4*)&w_pack[buf][q * PCKH + 8 * g2] =
            make_uint4(wpk[0], wpk[1], wpk[2], wpk[3]);
        *(uint4*)&w_pack[buf][q * PCKH + 8 * g2 + 4] =
            make_uint4(wpk[4], wpk[5], wpk[6], wpk[7]);

        // prefetch chunk c+1 h (LDG only)
        if (c < NN / 32 - 1) {
            hreg[0] = hsrc[(size_t)(c + 1) * DD * 4 + 2 * half];
            hreg[1] = hsrc[(size_t)(c + 1) * DD * 4 + 2 * half + 1];
        }

        __syncthreads();  // chunk c staged

        // MMA: 32q x 64o x 32m per warp (fp16, k16)
#pragma unroll
        for (int ks = 0; ks < 2; ks++) {
            int wcol = ks * 8 + 2 * tig;
            uint2 a0 = *(const uint2*)&w_pack[buf][(wq0 + frow) * PCKH + wcol];
            uint2 a1 = *(const uint2*)&w_pack[buf][(wq0 + 8 + frow) * PCKH + wcol];
            uint2 a2 = *(const uint2*)&w_pack[buf][(wq0 + 16 + frow) * PCKH + wcol];
            uint2 a3 = *(const uint2*)&w_pack[buf][(wq0 + 24 + frow) * PCKH + wcol];
#pragma unroll
            for (int nt = 0; nt < 8; nt++) {
                uint2 bb =
                    *(const uint2*)&h_pack[buf][(oh + nt * 8 + frow) * PCKH + wcol];
                mma_f16(acc[0][nt], a0.x, a1.x, a0.y, a1.y, bb.x, bb.y);
                mma_f16(acc[1][nt], a2.x, a3.x, a2.y, a3.y, bb.x, bb.y);
            }
        }

        // producer math for chunk c+1 (after MMA, before next barrier)
        if (c < NN / 32 - 1) PRODUCE_W(c + 1);
    }
#undef PRODUCE_W

    // epilogue: write fp16-packed concat words for outproj
#pragma unroll
    for (int qb = 0; qb < 2; qb++)
#pragma unroll
        for (int nt = 0; nt < 8; nt++) {
            int n = q0 + wq0 + qb * 16 + frow;
            int wrd = hh * 64 + ((oh + nt * 8) >> 1) + tig;
            unsigned* p = g_attp + ((size_t)b * NN + n) * 256 + wrd;
            p[0] = f2h2(acc[qb][nt][0], acc[qb][nt][1]);
            p[8 * 256] = f2h2(acc[qb][nt][2], acc[qb][nt][3]);
        }
}

// ============================================================
// Kernel 4: out = concat(att) @ Wp + bias, fp16 warp-MMA.
// ============================================================
__global__ void __launch_bounds__(256, 3)
k_outproj_f16(const float* __restrict__ bias, float* __restrict__ out) {
    __shared__ __align__(16) unsigned a_pack[2][QBO * PCKH];  // 12.3 KB
    __shared__ __align__(16) unsigned b_pack[2][DD * PCKH];   // 24.6 KB
    __shared__ float bias_s[DD];

    int tid = threadIdx.x, wid = tid >> 5, lane = tid & 31;
    int row0 = blockIdx.x * QBO;
    if (tid < DD) bias_s[tid] = bias[tid];
    __syncthreads();

    float acc[2][4][4];
#pragma unroll
    for (int i = 0; i < 2; i++)
#pragma unroll
        for (int j = 0; j < 4; j++)
#pragma unroll
            for (int k = 0; k < 4; k++) acc[i][j][k] = 0.f;

    int a_row = (tid >> 6) * 16 + ((tid >> 1) & 15);
    int a_quad = (tid & 1) + 2 * ((tid >> 5) & 1);
    const uint4* asrc =
        (const uint4*)(g_attp + (size_t)(row0 + a_row) * 256) + a_quad;

    int b_col = tid >> 1, b_half = tid & 1;
    const uint4* bsrc = (const uint4*)&g_wph[b_col][0];

    int wq0 = (wid >> 2) * 32, oh = (wid & 3) * 32;
    int frow = lane >> 2, tig = lane & 3, fcol = tig * 2;

    uint4 areg = asrc[0];
    uint4 breg0 = bsrc[b_half];
    uint4 breg1 = bsrc[2 + b_half];

    for (int c = 0; c < 16; c++) {
        int buf = c & 1;
        *(uint4*)&a_pack[buf][a_row * PCKH + a_quad * 4] = areg;
        *(uint4*)&b_pack[buf][b_col * PCKH + 4 * b_half] = breg0;
        *(uint4*)&b_pack[buf][b_col * PCKH + 8 + 4 * b_half] = breg1;

        if (c < 15) {
            areg = asrc[(c + 1) * 4];
            breg0 = bsrc[(c + 1) * 4 + b_half];
            breg1 = bsrc[(c + 1) * 4 + 2 + b_half];
        }
        __syncthreads();

#pragma unroll
        for (int ks = 0; ks < 2; ks++) {
            int wcol = ks * 8 + 2 * tig;
            uint2 aA0 = *(const uint2*)&a_pack[buf][(wq0 + frow) * PCKH + wcol];
            uint2 aA1 = *(const uint2*)&a_pack[buf][(wq0 + 8 + frow) * PCKH + wcol];
            uint2 aB0 = *(const uint2*)&a_pack[buf][(wq0 + 16 + frow) * PCKH + wcol];
            uint2 aB1 = *(const uint2*)&a_pack[buf][(wq0 + 24 + frow) * PCKH + wcol];
#pragma unroll
            for (int nt = 0; nt < 4; nt++) {
                uint2 bb =
                    *(const uint2*)&b_pack[buf][(oh + nt * 8 + frow) * PCKH + wcol];
                mma_f16(acc[0][nt], aA0.x, aA1.x, aA0.y, aA1.y, bb.x, bb.y);
                mma_f16(acc[1][nt], aB0.x, aB1.x, aB0.y, aB1.y, bb.x, bb.y);
            }
        }
    }

#pragma unroll
    for (int qb = 0; qb < 2; qb++)
#pragma unroll
        for (int nt = 0; nt < 4; nt++) {
            int rr = row0 + wq0 + qb * 16 + frow;
            int oo = oh + nt * 8 + fcol;
            float b0 = bias_s[oo], b1 = bias_s[oo + 1];
            float* p0 = out + (size_t)rr * DD + oo;
            *(float2*)p0 = make_float2(acc[qb][nt][0] + b0, acc[qb][nt][1] + b1);
            *(float2*)(p0 + (size_t)8 * DD) =
                make_float2(acc[qb][nt][2] + b0, acc[qb][nt][3] + b1);
        }
}

// ============================================================
extern "C" void kernel_launch(void* const* d_in, const int* in_sizes, int n_in,
                              void* d_out, int out_size) {
    const float* x    = (const float*)d_in[0];
    const int*   adj  = (const int*)d_in[1];
    const float* W    = (const float*)d_in[2];
    const float* a    = (const float*)d_in[3];
    const float* Wp   = (const float*)d_in[4];
    const float* bias = (const float*)d_in[5];

    const size_t OUT_E = (size_t)BB * NN * DD;
    const size_t AL_E  = (size_t)BB * HH * NN * NN;

    float* outp = nullptr;
    float* alphap = nullptr;
    int write_alpha = 0, write_out = 0;

    if ((size_t)out_size >= OUT_E + AL_E) {
        outp = (float*)d_out;
        alphap = (float*)d_out + OUT_E;
        write_alpha = 1;
        write_out = 1;
    } else if ((size_t)out_size >= AL_E) {
        alphap = (float*)d_out;
        write_alpha = 1;
    } else {
        outp = (float*)d_out;
        write_out = 1;
    }
    if (!alphap) alphap = g_h;  // dummy, never stored to when !write_alpha

    // k_attn is launch #4 so ncu (-s based) profiles it
    k_packadj<<<(BB * NN) / 8, 256>>>(adj);
    k_project<<<dim3(NN / 16, BB), 256>>>(x, W);
    k_scores<<<(BB * HH * NN * 32) / 256, 256>>>(a);
    k_attn_mma<<<dim3(NN / QB, HH, BB), 256>>>(alphap, write_alpha);
    if (write_out) {
        k_prepw<<<128, 256>>>(Wp);
        k_outproj_f16<<<(BB * NN) / QBO, 256>>>(bias, outp);
    }
}